// round 1
// baseline (speedup 1.0000x reference)
#include <cuda_runtime.h>
#include <math.h>

#define BB 2048
#define TT 128
#define DD 32
#define HH 256
#define SS 39
#define PMM 12
#define KK (DD + HH)      /* 288 */
#define G3 (3 * HH)       /* 768 */

// ---------------- device scratch (static, no allocation) ----------------
__device__ float g_Wk[KK * G3];        // packed weights, layout [k][j], j = gate*256 + h
__device__ float g_bias[G3];           // bf|bg|bo
__device__ float g_ig[HH * BB];        // static input gate, transposed [h][b]
__device__ float g_x[TT * DD * BB];    // x transposed to [t][d][b]
__device__ float g_h[2][HH * BB];      // hidden state ping-pong, transposed [h][b]
__device__ float g_c[HH * BB];         // cell state, transposed [h][b]
__device__ float g_weff[HH + PMM];     // collapsed head weights (Wd1 @ Wd0)
__device__ float g_beff;               // collapsed head bias

// ---------------- prep: pack gate weights + biases ----------------
__global__ void prep_pack(const float* __restrict__ Wf_i, const float* __restrict__ Wf_h, const float* __restrict__ bf,
                          const float* __restrict__ Wg_i, const float* __restrict__ Wg_h, const float* __restrict__ bg,
                          const float* __restrict__ Wo_i, const float* __restrict__ Wo_h, const float* __restrict__ bo)
{
    int idx = blockIdx.x * blockDim.x + threadIdx.x;
    if (idx < KK * G3) {
        int k = idx / G3;
        int j = idx - k * G3;
        int gate = j >> 8;
        int h = j & 255;
        const float* Wi = (gate == 0) ? Wf_i : (gate == 1) ? Wg_i : Wo_i;
        const float* Wh = (gate == 0) ? Wf_h : (gate == 1) ? Wg_h : Wo_h;
        g_Wk[idx] = (k < DD) ? Wi[h * DD + k] : Wh[h * HH + (k - DD)];
    }
    if (idx < G3) {
        int gate = idx >> 8;
        int h = idx & 255;
        const float* bb = (gate == 0) ? bf : (gate == 1) ? bg : bo;
        g_bias[idx] = bb[h];
    }
}

// ---------------- prep: static input gate i = sigmoid(x_s @ Wu^T + bu) ----------------
__global__ void prep_igate(const float* __restrict__ latlons, const float* __restrict__ yearly,
                           const float* __restrict__ Wu, const float* __restrict__ bu)
{
    int idx = blockIdx.x * blockDim.x + threadIdx.x;   // idx = h*B + b
    if (idx >= HH * BB) return;
    int b = idx & (BB - 1);
    int h = idx >> 11;
    const float* w = Wu + h * SS;
    float s = bu[h];
    s += w[0] * latlons[b * 2 + 0];
    s += w[1] * latlons[b * 2 + 1];
    #pragma unroll
    for (int i = 0; i < 37; i++) s += w[2 + i] * yearly[b * 37 + i];
    g_ig[idx] = 1.0f / (1.0f + expf(-s));
}

// ---------------- prep: transpose x [B,T,D] -> [T,D,B] ----------------
__global__ void prep_x(const float* __restrict__ x)
{
    __shared__ float s[32][33];
    int t = blockIdx.y;
    int b0 = blockIdx.x * 32;
    int tx = threadIdx.x, ty = threadIdx.y;
    // read x[b0+ty][t][tx]  (coalesced in tx)
    s[ty][tx] = x[(size_t)(b0 + ty) * (TT * DD) + (size_t)t * DD + tx];
    __syncthreads();
    // write g_x[t][ty][b0+tx]  (coalesced in tx)
    g_x[(size_t)t * (DD * BB) + (size_t)ty * BB + b0 + tx] = s[tx][ty];
}

// ---------------- prep: collapse dense head (no nonlinearity between layers) ----------------
__global__ void prep_head(const float* __restrict__ Wd0, const float* __restrict__ bd0,
                          const float* __restrict__ Wd1, const float* __restrict__ bd1)
{
    int idx = threadIdx.x;
    if (idx < HH + PMM) {
        float s = 0.0f;
        for (int m = 0; m < 256; m++) s += Wd1[m] * Wd0[m * (HH + PMM) + idx];
        g_weff[idx] = s;
    }
    if (idx == HH + PMM) {
        float s = bd1[0];
        for (int m = 0; m < 256; m++) s += Wd1[m] * bd0[m];
        g_beff = s;
    }
}

// ---------------- prep: zero initial h, c ----------------
__global__ void prep_zero()
{
    int idx = blockIdx.x * blockDim.x + threadIdx.x;
    if (idx < HH * BB) {
        g_h[0][idx] = 0.0f;
        g_c[idx] = 0.0f;
    }
}

// ---------------- one recurrent step: fused GEMM [2048,288]x[288,768] + gates ----------------
// CTA tile: 64 batch x 64 hidden x 3 gates. Grid (32,4) = 128 CTAs.
// Thread micro-tile: tx -> 4 contiguous batch cols, ty -> 4 hidden rows, 3 gates.
__global__ void __launch_bounds__(256, 1) step_kernel(int t, int parity)
{
    __shared__ __align__(16) float As[32][64];        // [k][b]
    __shared__ __align__(16) float Bs[3][32][64];     // [gate][k][h]

    const int tid = threadIdx.x;
    const int tx = tid & 15;          // batch direction
    const int ty = tid >> 4;          // hidden direction
    const int b_base = blockIdx.x * 64;
    const int h_base = blockIdx.y * 64;

    const float* __restrict__ hin = g_h[parity];
    float* __restrict__ hout = g_h[parity ^ 1];

    float acc[3][4][4];
    #pragma unroll
    for (int g = 0; g < 3; g++)
        #pragma unroll
        for (int i = 0; i < 4; i++)
            #pragma unroll
            for (int j = 0; j < 4; j++) acc[g][i][j] = 0.0f;

    const float* xsrc = g_x + (size_t)t * (DD * BB);

    for (int kc = 0; kc < KK; kc += 32) {
        // ---- stage A tile [32k x 64b] ----
        #pragma unroll
        for (int i = 0; i < 2; i++) {
            int idx = tid + i * 256;              // 512 float4 slots
            int kk = idx >> 4;
            int bb4 = (idx & 15) << 2;
            int k = kc + kk;
            const float* src = (k < DD)
                ? (xsrc + (size_t)k * BB + b_base + bb4)
                : (hin + (size_t)(k - DD) * BB + b_base + bb4);
            *(float4*)&As[kk][bb4] = *(const float4*)src;
        }
        // ---- stage B tiles [3g x 32k x 64h] ----
        #pragma unroll
        for (int i = 0; i < 6; i++) {
            int idx = tid + i * 256;              // 1536 float4 slots
            int g = idx >> 9;
            int rem = idx & 511;
            int kk = rem >> 4;
            int hh4 = (rem & 15) << 2;
            *(float4*)&Bs[g][kk][hh4] =
                *(const float4*)(g_Wk + (size_t)(kc + kk) * G3 + g * HH + h_base + hh4);
        }
        __syncthreads();

        // ---- 32 x (48 FFMA) per thread ----
        #pragma unroll
        for (int kk = 0; kk < 32; kk++) {
            float4 a4 = *(const float4*)&As[kk][tx * 4];
            float4 w0 = *(const float4*)&Bs[0][kk][ty * 4];
            float4 w1 = *(const float4*)&Bs[1][kk][ty * 4];
            float4 w2 = *(const float4*)&Bs[2][kk][ty * 4];
            float av[4]  = {a4.x, a4.y, a4.z, a4.w};
            float w0v[4] = {w0.x, w0.y, w0.z, w0.w};
            float w1v[4] = {w1.x, w1.y, w1.z, w1.w};
            float w2v[4] = {w2.x, w2.y, w2.z, w2.w};
            #pragma unroll
            for (int i = 0; i < 4; i++)
                #pragma unroll
                for (int j = 0; j < 4; j++) {
                    acc[0][i][j] = fmaf(w0v[i], av[j], acc[0][i][j]);
                    acc[1][i][j] = fmaf(w1v[i], av[j], acc[1][i][j]);
                    acc[2][i][j] = fmaf(w2v[i], av[j], acc[2][i][j]);
                }
        }
        __syncthreads();
    }

    // ---- epilogue: gate nonlinearities + state update (coalesced float4 in b) ----
    const int bg0 = b_base + tx * 4;
    #pragma unroll
    for (int i = 0; i < 4; i++) {
        int hg = h_base + ty * 4 + i;
        float bf = g_bias[hg];
        float bgg = g_bias[HH + hg];
        float bo = g_bias[2 * HH + hg];
        size_t base = (size_t)hg * BB + bg0;
        float4 cv = *(float4*)&g_c[base];
        float4 iv = *(const float4*)&g_ig[base];
        float cold[4] = {cv.x, cv.y, cv.z, cv.w};
        float igv[4]  = {iv.x, iv.y, iv.z, iv.w};
        float cn[4], hv[4];
        #pragma unroll
        for (int j = 0; j < 4; j++) {
            float f = 1.0f / (1.0f + expf(-(acc[0][i][j] + bf)));
            float gg = tanhf(acc[1][i][j] + bgg);
            float o = 1.0f / (1.0f + expf(-(acc[2][i][j] + bo)));
            float c1 = f * cold[j] + igv[j] * gg;
            cn[j] = c1;
            hv[j] = o * tanhf(c1);
        }
        *(float4*)&g_c[base] = make_float4(cn[0], cn[1], cn[2], cn[3]);
        *(float4*)&hout[base] = make_float4(hv[0], hv[1], hv[2], hv[3]);
    }
}

// ---------------- head: out[b] = dot(h_last||pred_month, w_eff) + b_eff ----------------
__global__ void head_kernel(const float* __restrict__ pm, float* __restrict__ out)
{
    int b = blockIdx.x * blockDim.x + threadIdx.x;
    if (b >= BB) return;
    float s = g_beff;
    const float* hfin = g_h[0];   // T=128 even -> final state lands in buffer 0
    #pragma unroll 8
    for (int k = 0; k < HH; k++) s += hfin[(size_t)k * BB + b] * g_weff[k];
    #pragma unroll
    for (int k = 0; k < PMM; k++) s += pm[b * PMM + k] * g_weff[HH + k];
    out[b] = s;
}

// ---------------- launch ----------------
extern "C" void kernel_launch(void* const* d_in, const int* in_sizes, int n_in,
                              void* d_out, int out_size)
{
    const float* x       = (const float*)d_in[0];
    const float* latlons = (const float*)d_in[1];
    const float* yearly  = (const float*)d_in[2];
    const float* pm      = (const float*)d_in[3];
    const float* Wf_i    = (const float*)d_in[4];
    const float* Wf_h    = (const float*)d_in[5];
    const float* bf      = (const float*)d_in[6];
    const float* Wu      = (const float*)d_in[7];
    const float* bu      = (const float*)d_in[8];
    const float* Wg_i    = (const float*)d_in[9];
    const float* Wg_h    = (const float*)d_in[10];
    const float* bg      = (const float*)d_in[11];
    const float* Wo_i    = (const float*)d_in[12];
    const float* Wo_h    = (const float*)d_in[13];
    const float* bo      = (const float*)d_in[14];
    const float* Wd0     = (const float*)d_in[15];
    const float* bd0     = (const float*)d_in[16];
    const float* Wd1     = (const float*)d_in[17];
    const float* bd1     = (const float*)d_in[18];

    prep_pack<<<(KK * G3 + 255) / 256, 256>>>(Wf_i, Wf_h, bf, Wg_i, Wg_h, bg, Wo_i, Wo_h, bo);
    prep_igate<<<(HH * BB + 255) / 256, 256>>>(latlons, yearly, Wu, bu);
    prep_x<<<dim3(BB / 32, TT), dim3(32, 32)>>>(x);
    prep_head<<<1, 512>>>(Wd0, bd0, Wd1, bd1);
    prep_zero<<<(HH * BB + 255) / 256, 256>>>();

    for (int t = 0; t < TT; t++) {
        step_kernel<<<dim3(BB / 64, HH / 64), 256>>>(t, t & 1);
    }

    head_kernel<<<(BB + 255) / 256, 256>>>(pm, (float*)d_out);
}

// round 3
// speedup vs baseline: 1.1112x; 1.1112x over previous
#include <cuda_runtime.h>
#include <cuda_bf16.h>
#include <math.h>
#include <stdint.h>

#define BB 2048
#define TT 128
#define DD 32
#define HH 256
#define SS 39
#define PMM 12
#define KS 896              /* [hi(x|h) 288 | lo(x|h) 288 | hi dup 288 | pad 32] */
#define NTOT 768            /* j = h*3 + gate (gate-interleaved) */
#define KB 64
#define NCHUNK (KS / KB)    /* 14 */

/* smem layout (bytes) */
#define A_PITCH 144         /* 72 bf16 (64 data + 8 pad), odd x 16B */
#define B_PITCH 208         /* 104 bf16 (96 data + 8 pad), odd x 16B */
#define A_STAGE (128 * A_PITCH)      /* 18432 */
#define B_STAGE (64 * B_PITCH)       /* 13312 */
#define B_ORIGIN (2 * A_STAGE)       /* 36864 */
#define C_PITCH 100                  /* fp32 elems per row */
#define HS_ORIGIN (128 * C_PITCH * 4)/* 51200 */
#define HS_PITCH 136                 /* uint32 per row */
#define SMEM_TOTAL (HS_ORIGIN + 32 * HS_PITCH * 4)  /* 68608 */

// ---------------- device scratch ----------------
__device__ __nv_bfloat16 g_X[2][BB * KS];                 // activations [b][k], ping-pong
__device__ __nv_bfloat16 g_W[KS * NTOT];                  // weights [k][j], j = h*3+gate
__device__ __nv_bfloat16 g_xsplit[(size_t)TT * BB * 64];  // per-t x: [t][b][hi32|lo32]
__device__ float g_bias[NTOT];                            // interleaved [h*3+gate]
__device__ float g_ig[HH * BB];                           // input gate [h][b]
__device__ float g_c[HH * BB];                            // cell state [h][b]
__device__ float g_weff[HH + PMM];
__device__ float g_beff;

// ---------------- asm helpers (sm_80-safe) ----------------
__device__ __forceinline__ uint32_t smem_u32(const void* p) {
    uint32_t a;
    asm("{ .reg .u64 t; cvta.to.shared.u64 t, %1; cvt.u32.u64 %0, t; }" : "=r"(a) : "l"(p));
    return a;
}
__device__ __forceinline__ void cp16(uint32_t dst, const void* src) {
    asm volatile("cp.async.cg.shared.global [%0], [%1], 16;" :: "r"(dst), "l"(src) : "memory");
}
__device__ __forceinline__ void cp_commit() {
    asm volatile("cp.async.commit_group;" ::: "memory");
}
template <int N>
__device__ __forceinline__ void cp_wait() {
    asm volatile("cp.async.wait_group %0;" :: "n"(N) : "memory");
}
__device__ __forceinline__ void ldm_x4(uint32_t* r, uint32_t addr) {
    asm volatile("ldmatrix.sync.aligned.m8n8.x4.shared.b16 {%0,%1,%2,%3}, [%4];"
                 : "=r"(r[0]), "=r"(r[1]), "=r"(r[2]), "=r"(r[3]) : "r"(addr));
}
__device__ __forceinline__ void ldm_x2t(uint32_t* r, uint32_t addr) {
    asm volatile("ldmatrix.sync.aligned.m8n8.x2.trans.shared.b16 {%0,%1}, [%2];"
                 : "=r"(r[0]), "=r"(r[1]) : "r"(addr));
}
__device__ __forceinline__ void mma16816(float* d, const uint32_t* a, const uint32_t* b) {
    asm volatile(
        "mma.sync.aligned.m16n8k16.row.col.f32.bf16.bf16.f32 "
        "{%0,%1,%2,%3}, {%4,%5,%6,%7}, {%8,%9}, {%0,%1,%2,%3};"
        : "+f"(d[0]), "+f"(d[1]), "+f"(d[2]), "+f"(d[3])
        : "r"(a[0]), "r"(a[1]), "r"(a[2]), "r"(a[3]), "r"(b[0]), "r"(b[1]));
}

// ---------------- prep kernels ----------------
__global__ void prep_Wsplit(const float* __restrict__ Wf_i, const float* __restrict__ Wf_h,
                            const float* __restrict__ Wg_i, const float* __restrict__ Wg_h,
                            const float* __restrict__ Wo_i, const float* __restrict__ Wo_h)
{
    int idx = blockIdx.x * blockDim.x + threadIdx.x;
    if (idx >= KS * NTOT) return;
    int k = idx / NTOT;
    int j = idx - k * NTOT;
    if (k >= 864) { g_W[idx] = __float2bfloat16(0.0f); return; }
    int h = j / 3, gate = j % 3;
    int ks = (k < 288) ? k : (k < 576 ? k - 288 : k - 576);
    const float* Wi = (gate == 0) ? Wf_i : (gate == 1) ? Wg_i : Wo_i;
    const float* Wh = (gate == 0) ? Wf_h : (gate == 1) ? Wg_h : Wo_h;
    float w = (ks < DD) ? Wi[h * DD + ks] : Wh[h * HH + (ks - DD)];
    __nv_bfloat16 hi = __float2bfloat16(w);
    g_W[idx] = (k < 576) ? hi : __float2bfloat16(w - __bfloat162float(hi));
}

__global__ void prep_bias(const float* __restrict__ bf, const float* __restrict__ bg, const float* __restrict__ bo)
{
    int idx = blockIdx.x * blockDim.x + threadIdx.x;
    if (idx >= NTOT) return;
    int h = idx / 3, gate = idx % 3;
    const float* b = (gate == 0) ? bf : (gate == 1) ? bg : bo;
    g_bias[idx] = b[h];
}

__global__ void prep_xsplit(const float* __restrict__ x)
{
    size_t idx = (size_t)blockIdx.x * blockDim.x + threadIdx.x;
    if (idx >= (size_t)TT * BB * DD) return;
    int k = idx % DD;
    size_t tb = idx / DD;
    int b = tb % BB;
    int t = tb / BB;
    float v = x[(size_t)b * (TT * DD) + (size_t)t * DD + k];
    __nv_bfloat16 hi = __float2bfloat16(v);
    __nv_bfloat16 lo = __float2bfloat16(v - __bfloat162float(hi));
    size_t base = ((size_t)t * BB + b) * 64;
    g_xsplit[base + k] = hi;
    g_xsplit[base + 32 + k] = lo;
}

__global__ void prep_X0(const float* __restrict__ x)
{
    size_t idx = (size_t)blockIdx.x * blockDim.x + threadIdx.x;
    if (idx >= (size_t)BB * KS) return;
    int k = idx % KS;
    int b = idx / KS;
    g_X[1][idx] = __float2bfloat16(0.0f);
    float v;
    __nv_bfloat16 out = __float2bfloat16(0.0f);
    if (k < DD) {
        v = x[(size_t)b * (TT * DD) + k];
        out = __float2bfloat16(v);
    } else if (k >= 288 && k < 288 + DD) {
        v = x[(size_t)b * (TT * DD) + (k - 288)];
        __nv_bfloat16 hi = __float2bfloat16(v);
        out = __float2bfloat16(v - __bfloat162float(hi));
    } else if (k >= 576 && k < 576 + DD) {
        v = x[(size_t)b * (TT * DD) + (k - 576)];
        out = __float2bfloat16(v);
    }
    g_X[0][idx] = out;
}

__global__ void prep_czero()
{
    int idx = blockIdx.x * blockDim.x + threadIdx.x;
    if (idx < HH * BB) g_c[idx] = 0.0f;
}

__global__ void prep_igate(const float* __restrict__ latlons, const float* __restrict__ yearly,
                           const float* __restrict__ Wu, const float* __restrict__ bu)
{
    int idx = blockIdx.x * blockDim.x + threadIdx.x;
    if (idx >= HH * BB) return;
    int b = idx & (BB - 1);
    int h = idx >> 11;
    const float* w = Wu + h * SS;
    float s = bu[h];
    s += w[0] * latlons[b * 2 + 0];
    s += w[1] * latlons[b * 2 + 1];
    #pragma unroll
    for (int i = 0; i < 37; i++) s += w[2 + i] * yearly[b * 37 + i];
    g_ig[idx] = 1.0f / (1.0f + expf(-s));
}

__global__ void prep_head(const float* __restrict__ Wd0, const float* __restrict__ bd0,
                          const float* __restrict__ Wd1, const float* __restrict__ bd1)
{
    int idx = threadIdx.x;
    if (idx < HH + PMM) {
        float s = 0.0f;
        for (int m = 0; m < 256; m++) s += Wd1[m] * Wd0[m * (HH + PMM) + idx];
        g_weff[idx] = s;
    }
    if (idx == HH + PMM) {
        float s = bd1[0];
        for (int m = 0; m < 256; m++) s += Wd1[m] * bd0[m];
        g_beff = s;
    }
}

// ---------------- recurrent step (HMMA mma.sync) ----------------
// CTA: 128 batch x 96 j (= 32 h x 3 gates). Grid (16, 8). 8 warps = 2m x 4n.
__global__ void __launch_bounds__(256, 1) step_kernel(int t)
{
    extern __shared__ char smem[];
    const uint32_t sb = smem_u32(smem);
    const int tid = threadIdx.x;
    const int wid = tid >> 5;
    const int lane = tid & 31;
    const int wm = wid & 1;        // 0..1 (64 rows each)
    const int wn = wid >> 1;       // 0..3 (24 cols each)
    const int bm = blockIdx.x;     // batch tile 0..15
    const int jt = blockIdx.y;     // j tile 0..7 (h group of 32)
    const int b_base = bm * 128;

    const __nv_bfloat16* __restrict__ Xb = g_X[t & 1];

    float acc[4][3][4];
    #pragma unroll
    for (int mt = 0; mt < 4; mt++)
        #pragma unroll
        for (int nt = 0; nt < 3; nt++)
            #pragma unroll
            for (int q = 0; q < 4; q++) acc[mt][nt][q] = 0.0f;

    // per-thread cp.async slot precompute
    const int a_row = tid >> 1;               // with 2 iters pattern below
    // A: 1024 x 16B slots (128 rows x 8), B: 768 slots (64 rows x 12)

    // ---- stage loader ----
    auto load_stage = [&](int c, int st) {
        const int kc = c * KB;
        #pragma unroll
        for (int i = 0; i < 4; i++) {
            int slot = tid + i * 256;
            int row = slot >> 3;
            int cq = slot & 7;
            const void* src = Xb + (size_t)(b_base + row) * KS + kc + cq * 8;
            cp16(sb + st * A_STAGE + row * A_PITCH + cq * 16, src);
        }
        #pragma unroll
        for (int i = 0; i < 3; i++) {
            int slot = tid + i * 256;
            int row = slot / 12;
            int cq = slot - row * 12;
            const void* src = g_W + (size_t)(kc + row) * NTOT + jt * 96 + cq * 8;
            cp16(sb + B_ORIGIN + st * B_STAGE + row * B_PITCH + cq * 16, src);
        }
        cp_commit();
    };

    // per-thread ldmatrix base offsets
    const uint32_t a_off = (uint32_t)((wm * 64 + (lane & 15)) * A_PITCH + (lane >> 4) * 16);
    const uint32_t b_off = (uint32_t)((lane & 15) * B_PITCH + wn * 48);

    load_stage(0, 0);

    for (int c = 0; c < NCHUNK; c++) {
        int st = c & 1;
        if (c < NCHUNK - 1) {
            load_stage(c + 1, st ^ 1);
            cp_wait<1>();
        } else {
            cp_wait<0>();
        }
        __syncthreads();

        uint32_t aB = sb + st * A_STAGE + a_off;
        uint32_t bB = sb + B_ORIGIN + st * B_STAGE + b_off;
        #pragma unroll
        for (int kk = 0; kk < 4; kk++) {
            uint32_t af[4][4], bf[3][2];
            #pragma unroll
            for (int mt = 0; mt < 4; mt++) ldm_x4(af[mt], aB + mt * (16 * A_PITCH) + kk * 32);
            #pragma unroll
            for (int nt = 0; nt < 3; nt++) ldm_x2t(bf[nt], bB + kk * (16 * B_PITCH) + nt * 16);
            #pragma unroll
            for (int mt = 0; mt < 4; mt++)
                #pragma unroll
                for (int nt = 0; nt < 3; nt++)
                    mma16816(acc[mt][nt], af[mt], bf[nt]);
        }
        __syncthreads();
    }

    // ---- dump accumulators to smem C [128][C_PITCH] fp32 ----
    float* Cs = (float*)smem;
    {
        const int r0 = wm * 64 + (lane >> 2);
        const int c0 = wn * 24 + (lane & 3) * 2;
        #pragma unroll
        for (int mt = 0; mt < 4; mt++)
            #pragma unroll
            for (int nt = 0; nt < 3; nt++) {
                int r = r0 + mt * 16;
                int cc = c0 + nt * 8;
                Cs[r * C_PITCH + cc]           = acc[mt][nt][0];
                Cs[r * C_PITCH + cc + 1]       = acc[mt][nt][1];
                Cs[(r + 8) * C_PITCH + cc]     = acc[mt][nt][2];
                Cs[(r + 8) * C_PITCH + cc + 1] = acc[mt][nt][3];
            }
    }
    __syncthreads();

    // ---- gates + state update ----
    uint32_t* Hs = (uint32_t*)(smem + HS_ORIGIN);   // [32][HS_PITCH] packed (hi,lo) bf16
    #pragma unroll
    for (int i = 0; i < 16; i++) {
        int idx = i * 256 + tid;
        int b_l = idx & 127;
        int h_l = idx >> 7;
        int hg = jt * 32 + h_l;
        float fp = Cs[b_l * C_PITCH + h_l * 3 + 0] + g_bias[hg * 3 + 0];
        float gp = Cs[b_l * C_PITCH + h_l * 3 + 1] + g_bias[hg * 3 + 1];
        float op = Cs[b_l * C_PITCH + h_l * 3 + 2] + g_bias[hg * 3 + 2];
        float f = 1.0f / (1.0f + expf(-fp));
        float g = tanhf(gp);
        float o = 1.0f / (1.0f + expf(-op));
        size_t off = (size_t)hg * BB + b_base + b_l;
        float c1 = f * g_c[off] + g_ig[off] * g;
        g_c[off] = c1;
        float hv = o * tanhf(c1);
        __nv_bfloat16 hi = __float2bfloat16(hv);
        __nv_bfloat16 lo = __float2bfloat16(hv - __bfloat162float(hi));
        __nv_bfloat162 pk; pk.x = hi; pk.y = lo;
        Hs[h_l * HS_PITCH + b_l] = *(uint32_t*)&pk;
    }
    __syncthreads();

    // ---- write h (hi / dup / lo) into next X buffer ----
    if (tid < 128) {
        const int b = b_base + tid;
        __nv_bfloat16* Xo = &g_X[(t + 1) & 1][(size_t)b * KS];
        const int h0 = jt * 32;
        #pragma unroll
        for (int i = 0; i < 4; i++) {          // 4 x 8 h values
            uint4 vh, vl;
            uint32_t* ph = (uint32_t*)&vh;
            uint32_t* pl = (uint32_t*)&vl;
            #pragma unroll
            for (int q = 0; q < 4; q++) {
                uint32_t p0 = Hs[(i * 8 + q * 2) * HS_PITCH + tid];
                uint32_t p1 = Hs[(i * 8 + q * 2 + 1) * HS_PITCH + tid];
                // p = (hi | lo<<16); build hi pair and lo pair
                ph[q] = (p0 & 0xFFFFu) | (p1 << 16);
                pl[q] = (p0 >> 16) | (p1 & 0xFFFF0000u);
            }
            *(uint4*)(Xo + 32  + h0 + i * 8) = vh;
            *(uint4*)(Xo + 608 + h0 + i * 8) = vh;
            *(uint4*)(Xo + 320 + h0 + i * 8) = vl;
        }
        if (jt == 0 && t < TT - 1) {
            const __nv_bfloat16* xs = g_xsplit + ((size_t)(t + 1) * BB + b) * 64;
            #pragma unroll
            for (int i = 0; i < 4; i++) {
                uint4 v = *(const uint4*)(xs + i * 8);
                *(uint4*)(Xo + i * 8) = v;
                *(uint4*)(Xo + 576 + i * 8) = v;
            }
            #pragma unroll
            for (int i = 0; i < 4; i++) {
                uint4 v = *(const uint4*)(xs + 32 + i * 8);
                *(uint4*)(Xo + 288 + i * 8) = v;
            }
        }
    }
}

// ---------------- head ----------------
__global__ void head_kernel(const float* __restrict__ pm, float* __restrict__ out)
{
    int b = blockIdx.x * blockDim.x + threadIdx.x;
    if (b >= BB) return;
    const __nv_bfloat16* Xrow = &g_X[0][(size_t)b * KS];   // T=128 even -> final h in buffer 0
    float s = g_beff;
    #pragma unroll 8
    for (int k = 0; k < HH; k++) {
        float h = __bfloat162float(Xrow[32 + k]) + __bfloat162float(Xrow[320 + k]);
        s += h * g_weff[k];
    }
    #pragma unroll
    for (int k = 0; k < PMM; k++) s += pm[b * PMM + k] * g_weff[HH + k];
    out[b] = s;
}

// ---------------- launch ----------------
extern "C" void kernel_launch(void* const* d_in, const int* in_sizes, int n_in,
                              void* d_out, int out_size)
{
    const float* x       = (const float*)d_in[0];
    const float* latlons = (const float*)d_in[1];
    const float* yearly  = (const float*)d_in[2];
    const float* pm      = (const float*)d_in[3];
    const float* Wf_i    = (const float*)d_in[4];
    const float* Wf_h    = (const float*)d_in[5];
    const float* bf      = (const float*)d_in[6];
    const float* Wu      = (const float*)d_in[7];
    const float* bu      = (const float*)d_in[8];
    const float* Wg_i    = (const float*)d_in[9];
    const float* Wg_h    = (const float*)d_in[10];
    const float* bg      = (const float*)d_in[11];
    const float* Wo_i    = (const float*)d_in[12];
    const float* Wo_h    = (const float*)d_in[13];
    const float* bo      = (const float*)d_in[14];
    const float* Wd0     = (const float*)d_in[15];
    const float* bd0     = (const float*)d_in[16];
    const float* Wd1     = (const float*)d_in[17];
    const float* bd1     = (const float*)d_in[18];

    static bool attr_set = false;
    if (!attr_set) {
        cudaFuncSetAttribute(step_kernel, cudaFuncAttributeMaxDynamicSharedMemorySize, SMEM_TOTAL);
        attr_set = true;
    }

    prep_Wsplit<<<(KS * NTOT + 255) / 256, 256>>>(Wf_i, Wf_h, Wg_i, Wg_h, Wo_i, Wo_h);
    prep_bias<<<3, 256>>>(bf, bg, bo);
    prep_xsplit<<<(int)(((size_t)TT * BB * DD + 255) / 256), 256>>>(x);
    prep_X0<<<(int)(((size_t)BB * KS + 255) / 256), 256>>>(x);
    prep_czero<<<(HH * BB + 255) / 256, 256>>>();
    prep_igate<<<(HH * BB + 255) / 256, 256>>>(latlons, yearly, Wu, bu);
    prep_head<<<1, 512>>>(Wd0, bd0, Wd1, bd1);

    for (int t = 0; t < TT; t++) {
        step_kernel<<<dim3(16, 8), 256, SMEM_TOTAL>>>(t);
    }

    head_kernel<<<(BB + 255) / 256, 256>>>(pm, (float*)d_out);
}

// round 4
// speedup vs baseline: 1.5658x; 1.4092x over previous
#include <cuda_runtime.h>
#include <cuda_fp16.h>
#include <math.h>
#include <stdint.h>

#define BB 2048
#define TT 128
#define DD 32
#define HH 256
#define SS 39
#define PMM 12
#define KS 576              /* [x_f16 32 | h_hi 256 | h_lo 256 | pad 32] */
#define NTOT 768            /* j = h*3 + gate (gate-interleaved) */
#define KB 64
#define NCHUNK (KS / KB)    /* 9 */
#define NSTAGE 3

/* smem layout (bytes) */
#define A_PITCH 144         /* 72 f16 (64 data + 8 pad), odd x 16B */
#define B_PITCH 208         /* 104 f16 (96 data + 8 pad), odd x 16B */
#define A_STAGE (128 * A_PITCH)          /* 18432 */
#define B_STAGE (64 * B_PITCH)           /* 13312 */
#define B_ORIGIN (NSTAGE * A_STAGE)      /* 55296 */
#define C_PITCH 100                      /* fp32 elems per row (overlaps stages) */
#define HS_ORIGIN (128 * C_PITCH * 4)    /* 51200 */
#define HS_PITCH 136                     /* uint32 per row */
#define SMEM_TOTAL (B_ORIGIN + NSTAGE * B_STAGE)   /* 95232 */

// ---------------- device scratch ----------------
__device__ __half g_X[2][BB * KS];                  // activations [b][k], ping-pong
__device__ __half g_W[KS * NTOT];                   // weights [k][j], j = h*3+gate
__device__ __half g_xsplit[(size_t)TT * BB * DD];   // per-t x fp16: [t][b][32]
__device__ float g_bias[NTOT];                      // interleaved [h*3+gate]
__device__ float g_ig[HH * BB];                     // input gate [h][b]
__device__ float g_c[HH * BB];                      // cell state [h][b]
__device__ float g_weff[HH + PMM];
__device__ float g_beff;

// ---------------- asm helpers (sm_80-safe) ----------------
__device__ __forceinline__ uint32_t smem_u32(const void* p) {
    uint32_t a;
    asm("{ .reg .u64 t; cvta.to.shared.u64 t, %1; cvt.u32.u64 %0, t; }" : "=r"(a) : "l"(p));
    return a;
}
__device__ __forceinline__ void cp16(uint32_t dst, const void* src) {
    asm volatile("cp.async.cg.shared.global [%0], [%1], 16;" :: "r"(dst), "l"(src) : "memory");
}
__device__ __forceinline__ void cp_commit() {
    asm volatile("cp.async.commit_group;" ::: "memory");
}
template <int N>
__device__ __forceinline__ void cp_wait() {
    asm volatile("cp.async.wait_group %0;" :: "n"(N) : "memory");
}
__device__ __forceinline__ void ldm_x4(uint32_t* r, uint32_t addr) {
    asm volatile("ldmatrix.sync.aligned.m8n8.x4.shared.b16 {%0,%1,%2,%3}, [%4];"
                 : "=r"(r[0]), "=r"(r[1]), "=r"(r[2]), "=r"(r[3]) : "r"(addr));
}
__device__ __forceinline__ void ldm_x2t(uint32_t* r, uint32_t addr) {
    asm volatile("ldmatrix.sync.aligned.m8n8.x2.trans.shared.b16 {%0,%1}, [%2];"
                 : "=r"(r[0]), "=r"(r[1]) : "r"(addr));
}
__device__ __forceinline__ void mma16816(float* d, const uint32_t* a, const uint32_t* b) {
    asm volatile(
        "mma.sync.aligned.m16n8k16.row.col.f32.f16.f16.f32 "
        "{%0,%1,%2,%3}, {%4,%5,%6,%7}, {%8,%9}, {%0,%1,%2,%3};"
        : "+f"(d[0]), "+f"(d[1]), "+f"(d[2]), "+f"(d[3])
        : "r"(a[0]), "r"(a[1]), "r"(a[2]), "r"(a[3]), "r"(b[0]), "r"(b[1]));
}

// ---------------- prep kernels ----------------
__global__ void prep_W(const float* __restrict__ Wf_i, const float* __restrict__ Wf_h,
                       const float* __restrict__ Wg_i, const float* __restrict__ Wg_h,
                       const float* __restrict__ Wo_i, const float* __restrict__ Wo_h)
{
    int idx = blockIdx.x * blockDim.x + threadIdx.x;
    if (idx >= KS * NTOT) return;
    int k = idx / NTOT;
    int j = idx - k * NTOT;
    if (k >= 544) { g_W[idx] = __float2half(0.0f); return; }
    int h = j / 3, gate = j % 3;
    const float* Wi = (gate == 0) ? Wf_i : (gate == 1) ? Wg_i : Wo_i;
    const float* Wh = (gate == 0) ? Wf_h : (gate == 1) ? Wg_h : Wo_h;
    float w;
    if (k < DD)        w = Wi[h * DD + k];
    else if (k < 288)  w = Wh[h * HH + (k - 32)];
    else               w = Wh[h * HH + (k - 288)];
    g_W[idx] = __float2half(w);
}

__global__ void prep_bias(const float* __restrict__ bf, const float* __restrict__ bg, const float* __restrict__ bo)
{
    int idx = blockIdx.x * blockDim.x + threadIdx.x;
    if (idx >= NTOT) return;
    int h = idx / 3, gate = idx % 3;
    const float* b = (gate == 0) ? bf : (gate == 1) ? bg : bo;
    g_bias[idx] = b[h];
}

__global__ void prep_xf16(const float* __restrict__ x)
{
    size_t idx = (size_t)blockIdx.x * blockDim.x + threadIdx.x;
    if (idx >= (size_t)TT * BB * DD) return;
    int k = idx % DD;
    size_t tb = idx / DD;
    int b = tb % BB;
    int t = tb / BB;
    g_xsplit[((size_t)t * BB + b) * DD + k] =
        __float2half(x[(size_t)b * (TT * DD) + (size_t)t * DD + k]);
}

__global__ void prep_X0(const float* __restrict__ x)
{
    size_t idx = (size_t)blockIdx.x * blockDim.x + threadIdx.x;
    if (idx >= (size_t)BB * KS) return;
    int k = idx % KS;
    int b = idx / KS;
    g_X[1][idx] = __float2half(0.0f);
    g_X[0][idx] = (k < DD) ? __float2half(x[(size_t)b * (TT * DD) + k]) : __float2half(0.0f);
}

__global__ void prep_czero()
{
    int idx = blockIdx.x * blockDim.x + threadIdx.x;
    if (idx < HH * BB) g_c[idx] = 0.0f;
}

__global__ void prep_igate(const float* __restrict__ latlons, const float* __restrict__ yearly,
                           const float* __restrict__ Wu, const float* __restrict__ bu)
{
    int idx = blockIdx.x * blockDim.x + threadIdx.x;
    if (idx >= HH * BB) return;
    int b = idx & (BB - 1);
    int h = idx >> 11;
    const float* w = Wu + h * SS;
    float s = bu[h];
    s += w[0] * latlons[b * 2 + 0];
    s += w[1] * latlons[b * 2 + 1];
    #pragma unroll
    for (int i = 0; i < 37; i++) s += w[2 + i] * yearly[b * 37 + i];
    g_ig[idx] = 1.0f / (1.0f + expf(-s));
}

__global__ void prep_head(const float* __restrict__ Wd0, const float* __restrict__ bd0,
                          const float* __restrict__ Wd1, const float* __restrict__ bd1)
{
    int idx = threadIdx.x;
    if (idx < HH + PMM) {
        float s = 0.0f;
        for (int m = 0; m < 256; m++) s += Wd1[m] * Wd0[m * (HH + PMM) + idx];
        g_weff[idx] = s;
    }
    if (idx == HH + PMM) {
        float s = bd1[0];
        for (int m = 0; m < 256; m++) s += Wd1[m] * bd0[m];
        g_beff = s;
    }
}

// ---------------- recurrent step (HMMA mma.sync, fp16 2-term split) ----------------
// CTA: 128 batch x 96 j (= 32 h x 3 gates). Grid (16, 8). 8 warps = 2m x 4n.
__global__ void __launch_bounds__(256, 1) step_kernel(int t)
{
    extern __shared__ char smem[];
    const uint32_t sb = smem_u32(smem);
    const int tid = threadIdx.x;
    const int wid = tid >> 5;
    const int lane = tid & 31;
    const int wm = wid & 1;        // 0..1 (64 rows each)
    const int wn = wid >> 1;       // 0..3 (24 cols each)
    const int bm = blockIdx.x;     // batch tile 0..15
    const int jt = blockIdx.y;     // j tile 0..7 (h group of 32)
    const int b_base = bm * 128;

    const __half* __restrict__ Xb = g_X[t & 1];

    float acc[4][3][4];
    #pragma unroll
    for (int mt = 0; mt < 4; mt++)
        #pragma unroll
        for (int nt = 0; nt < 3; nt++)
            #pragma unroll
            for (int q = 0; q < 4; q++) acc[mt][nt][q] = 0.0f;

    auto load_stage = [&](int c, int st) {
        const int kc = c * KB;
        #pragma unroll
        for (int i = 0; i < 4; i++) {
            int slot = tid + i * 256;
            int row = slot >> 3;
            int cq = slot & 7;
            const void* src = Xb + (size_t)(b_base + row) * KS + kc + cq * 8;
            cp16(sb + st * A_STAGE + row * A_PITCH + cq * 16, src);
        }
        #pragma unroll
        for (int i = 0; i < 3; i++) {
            int slot = tid + i * 256;
            int row = slot / 12;
            int cq = slot - row * 12;
            const void* src = g_W + (size_t)(kc + row) * NTOT + jt * 96 + cq * 8;
            cp16(sb + B_ORIGIN + st * B_STAGE + row * B_PITCH + cq * 16, src);
        }
        cp_commit();
    };

    const uint32_t a_off = (uint32_t)((wm * 64 + (lane & 15)) * A_PITCH + (lane >> 4) * 16);
    const uint32_t b_off = (uint32_t)((lane & 15) * B_PITCH + wn * 48);

    load_stage(0, 0);
    load_stage(1, 1);

    for (int c = 0; c < NCHUNK; c++) {
        const int st = c % NSTAGE;
        cp_wait<1>();
        __syncthreads();
        if (c + 2 < NCHUNK) load_stage(c + 2, (c + 2) % NSTAGE);
        else cp_commit();   // keep group count aligned

        uint32_t aB = sb + st * A_STAGE + a_off;
        uint32_t bB = sb + B_ORIGIN + st * B_STAGE + b_off;
        #pragma unroll
        for (int kk = 0; kk < 4; kk++) {
            uint32_t af[4][4], bf[3][2];
            #pragma unroll
            for (int mt = 0; mt < 4; mt++) ldm_x4(af[mt], aB + mt * (16 * A_PITCH) + kk * 32);
            #pragma unroll
            for (int nt = 0; nt < 3; nt++) ldm_x2t(bf[nt], bB + kk * (16 * B_PITCH) + nt * 16);
            #pragma unroll
            for (int mt = 0; mt < 4; mt++)
                #pragma unroll
                for (int nt = 0; nt < 3; nt++)
                    mma16816(acc[mt][nt], af[mt], bf[nt]);
        }
    }
    __syncthreads();

    // ---- dump accumulators to smem C [128][C_PITCH] fp32 (overlaps dead stages) ----
    float* Cs = (float*)smem;
    {
        const int r0 = wm * 64 + (lane >> 2);
        const int c0 = wn * 24 + (lane & 3) * 2;
        #pragma unroll
        for (int mt = 0; mt < 4; mt++)
            #pragma unroll
            for (int nt = 0; nt < 3; nt++) {
                int r = r0 + mt * 16;
                int cc = c0 + nt * 8;
                Cs[r * C_PITCH + cc]           = acc[mt][nt][0];
                Cs[r * C_PITCH + cc + 1]       = acc[mt][nt][1];
                Cs[(r + 8) * C_PITCH + cc]     = acc[mt][nt][2];
                Cs[(r + 8) * C_PITCH + cc + 1] = acc[mt][nt][3];
            }
    }
    __syncthreads();

    // ---- gates + state update ----
    uint32_t* Hs = (uint32_t*)(smem + HS_ORIGIN);   // [32][HS_PITCH] packed (hi,lo) fp16
    #pragma unroll
    for (int i = 0; i < 16; i++) {
        int idx = i * 256 + tid;
        int b_l = idx & 127;
        int h_l = idx >> 7;
        int hg = jt * 32 + h_l;
        float fp = Cs[b_l * C_PITCH + h_l * 3 + 0] + g_bias[hg * 3 + 0];
        float gp = Cs[b_l * C_PITCH + h_l * 3 + 1] + g_bias[hg * 3 + 1];
        float op = Cs[b_l * C_PITCH + h_l * 3 + 2] + g_bias[hg * 3 + 2];
        float f = 1.0f / (1.0f + expf(-fp));
        float g = tanhf(gp);
        float o = 1.0f / (1.0f + expf(-op));
        size_t off = (size_t)hg * BB + b_base + b_l;
        float c1 = f * g_c[off] + g_ig[off] * g;
        g_c[off] = c1;
        float hv = o * tanhf(c1);
        __half hi = __float2half(hv);
        __half lo = __float2half(hv - __half2float(hi));
        uint32_t pk = (uint32_t)*(uint16_t*)&hi | ((uint32_t)*(uint16_t*)&lo << 16);
        Hs[h_l * HS_PITCH + b_l] = pk;
    }
    __syncthreads();

    // ---- write h (hi at k=32+, lo at k=288+) into next X buffer ----
    if (tid < 128) {
        const int b = b_base + tid;
        __half* Xo = &g_X[(t + 1) & 1][(size_t)b * KS];
        const int h0 = jt * 32;
        #pragma unroll
        for (int i = 0; i < 4; i++) {          // 4 x 8 h values
            uint4 vh, vl;
            uint32_t* ph = (uint32_t*)&vh;
            uint32_t* pl = (uint32_t*)&vl;
            #pragma unroll
            for (int q = 0; q < 4; q++) {
                uint32_t p0 = Hs[(i * 8 + q * 2) * HS_PITCH + tid];
                uint32_t p1 = Hs[(i * 8 + q * 2 + 1) * HS_PITCH + tid];
                ph[q] = (p0 & 0xFFFFu) | (p1 << 16);
                pl[q] = (p0 >> 16) | (p1 & 0xFFFF0000u);
            }
            *(uint4*)(Xo + 32  + h0 + i * 8) = vh;
            *(uint4*)(Xo + 288 + h0 + i * 8) = vl;
        }
        if (jt == 0 && t < TT - 1) {
            const __half* xs = g_xsplit + ((size_t)(t + 1) * BB + b) * DD;
            #pragma unroll
            for (int i = 0; i < 4; i++)
                *(uint4*)(Xo + i * 8) = *(const uint4*)(xs + i * 8);
        }
    }
}

// ---------------- head ----------------
__global__ void head_kernel(const float* __restrict__ pm, float* __restrict__ out)
{
    int b = blockIdx.x * blockDim.x + threadIdx.x;
    if (b >= BB) return;
    const __half* Xrow = &g_X[0][(size_t)b * KS];   // T=128 even -> final h in buffer 0
    float s = g_beff;
    #pragma unroll 8
    for (int k = 0; k < HH; k++) {
        float h = __half2float(Xrow[32 + k]) + __half2float(Xrow[288 + k]);
        s += h * g_weff[k];
    }
    #pragma unroll
    for (int k = 0; k < PMM; k++) s += pm[b * PMM + k] * g_weff[HH + k];
    out[b] = s;
}

// ---------------- launch ----------------
extern "C" void kernel_launch(void* const* d_in, const int* in_sizes, int n_in,
                              void* d_out, int out_size)
{
    const float* x       = (const float*)d_in[0];
    const float* latlons = (const float*)d_in[1];
    const float* yearly  = (const float*)d_in[2];
    const float* pm      = (const float*)d_in[3];
    const float* Wf_i    = (const float*)d_in[4];
    const float* Wf_h    = (const float*)d_in[5];
    const float* bf      = (const float*)d_in[6];
    const float* Wu      = (const float*)d_in[7];
    const float* bu      = (const float*)d_in[8];
    const float* Wg_i    = (const float*)d_in[9];
    const float* Wg_h    = (const float*)d_in[10];
    const float* bg      = (const float*)d_in[11];
    const float* Wo_i    = (const float*)d_in[12];
    const float* Wo_h    = (const float*)d_in[13];
    const float* bo      = (const float*)d_in[14];
    const float* Wd0     = (const float*)d_in[15];
    const float* bd0     = (const float*)d_in[16];
    const float* Wd1     = (const float*)d_in[17];
    const float* bd1     = (const float*)d_in[18];

    static bool attr_set = false;
    if (!attr_set) {
        cudaFuncSetAttribute(step_kernel, cudaFuncAttributeMaxDynamicSharedMemorySize, SMEM_TOTAL);
        attr_set = true;
    }

    prep_W<<<(KS * NTOT + 255) / 256, 256>>>(Wf_i, Wf_h, Wg_i, Wg_h, Wo_i, Wo_h);
    prep_bias<<<3, 256>>>(bf, bg, bo);
    prep_xf16<<<(int)(((size_t)TT * BB * DD + 255) / 256), 256>>>(x);
    prep_X0<<<(int)(((size_t)BB * KS + 255) / 256), 256>>>(x);
    prep_czero<<<(HH * BB + 255) / 256, 256>>>();
    prep_igate<<<(HH * BB + 255) / 256, 256>>>(latlons, yearly, Wu, bu);
    prep_head<<<1, 512>>>(Wd0, bd0, Wd1, bd1);

    for (int t = 0; t < TT; t++) {
        step_kernel<<<dim3(16, 8), 256, SMEM_TOTAL>>>(t);
    }

    head_kernel<<<(BB + 255) / 256, 256>>>(pm, (float*)d_out);
}

// round 5
// speedup vs baseline: 1.9927x; 1.2726x over previous
#include <cuda_runtime.h>
#include <cuda_fp16.h>
#include <math.h>
#include <stdint.h>

#define BB 2048
#define TT 128
#define DD 32
#define HH 256
#define SS 39
#define PMM 12
#define KS 320              /* [x_f16 32 | h 256 | pad 32] */
#define NTOT 768            /* j = h*3 + gate (gate-interleaved) */
#define KB 64
#define NCHUNK (KS / KB)    /* 5 */
#define NSTAGE 3

/* smem layout (bytes) */
#define A_PITCH 144         /* 72 f16 (64 data + 8 pad), odd x 16B */
#define B_PITCH 208         /* 104 f16 (96 data + 8 pad), odd x 16B */
#define A_STAGE (128 * A_PITCH)          /* 18432 */
#define B_STAGE (64 * B_PITCH)           /* 13312 */
#define B_ORIGIN (NSTAGE * A_STAGE)      /* 55296 */
#define C_PITCH 100                      /* fp32 elems per row (overlaps stages) */
#define HS_ORIGIN (128 * C_PITCH * 4)    /* 51200 */
#define HS_PITCH 136                     /* uint32 per row */
#define SMEM_TOTAL (B_ORIGIN + NSTAGE * B_STAGE)   /* 95232 */

// ---------------- device scratch ----------------
__device__ __half g_X[2][BB * KS];                  // activations [b][k], ping-pong
__device__ __half g_W[KS * NTOT];                   // weights [k][j], j = h*3+gate
__device__ __half g_xf16[(size_t)TT * BB * DD];     // per-t x fp16: [t][b][32]
__device__ float g_bias[NTOT];                      // interleaved [h*3+gate]
__device__ float g_ig[HH * BB];                     // input gate [h][b]
__device__ float g_c[HH * BB];                      // cell state [h][b]
__device__ float g_weff[HH + PMM];
__device__ float g_beff;

// ---------------- asm helpers (sm_80-safe) ----------------
__device__ __forceinline__ uint32_t smem_u32(const void* p) {
    uint32_t a;
    asm("{ .reg .u64 t; cvta.to.shared.u64 t, %1; cvt.u32.u64 %0, t; }" : "=r"(a) : "l"(p));
    return a;
}
__device__ __forceinline__ void cp16(uint32_t dst, const void* src) {
    asm volatile("cp.async.cg.shared.global [%0], [%1], 16;" :: "r"(dst), "l"(src) : "memory");
}
__device__ __forceinline__ void cp_commit() {
    asm volatile("cp.async.commit_group;" ::: "memory");
}
template <int N>
__device__ __forceinline__ void cp_wait() {
    asm volatile("cp.async.wait_group %0;" :: "n"(N) : "memory");
}
__device__ __forceinline__ void ldm_x4(uint32_t* r, uint32_t addr) {
    asm volatile("ldmatrix.sync.aligned.m8n8.x4.shared.b16 {%0,%1,%2,%3}, [%4];"
                 : "=r"(r[0]), "=r"(r[1]), "=r"(r[2]), "=r"(r[3]) : "r"(addr));
}
__device__ __forceinline__ void ldm_x2t(uint32_t* r, uint32_t addr) {
    asm volatile("ldmatrix.sync.aligned.m8n8.x2.trans.shared.b16 {%0,%1}, [%2];"
                 : "=r"(r[0]), "=r"(r[1]) : "r"(addr));
}
__device__ __forceinline__ void mma16816(float* d, const uint32_t* a, const uint32_t* b) {
    asm volatile(
        "mma.sync.aligned.m16n8k16.row.col.f32.f16.f16.f32 "
        "{%0,%1,%2,%3}, {%4,%5,%6,%7}, {%8,%9}, {%0,%1,%2,%3};"
        : "+f"(d[0]), "+f"(d[1]), "+f"(d[2]), "+f"(d[3])
        : "r"(a[0]), "r"(a[1]), "r"(a[2]), "r"(a[3]), "r"(b[0]), "r"(b[1]));
}

// ---------------- prep kernels ----------------
__global__ void prep_W(const float* __restrict__ Wf_i, const float* __restrict__ Wf_h,
                       const float* __restrict__ Wg_i, const float* __restrict__ Wg_h,
                       const float* __restrict__ Wo_i, const float* __restrict__ Wo_h)
{
    int idx = blockIdx.x * blockDim.x + threadIdx.x;
    if (idx >= KS * NTOT) return;
    int k = idx / NTOT;
    int j = idx - k * NTOT;
    if (k >= 288) { g_W[idx] = __float2half(0.0f); return; }
    int h = j / 3, gate = j % 3;
    const float* Wi = (gate == 0) ? Wf_i : (gate == 1) ? Wg_i : Wo_i;
    const float* Wh = (gate == 0) ? Wf_h : (gate == 1) ? Wg_h : Wo_h;
    float w = (k < DD) ? Wi[h * DD + k] : Wh[h * HH + (k - 32)];
    g_W[idx] = __float2half(w);
}

__global__ void prep_bias(const float* __restrict__ bf, const float* __restrict__ bg, const float* __restrict__ bo)
{
    int idx = blockIdx.x * blockDim.x + threadIdx.x;
    if (idx >= NTOT) return;
    int h = idx / 3, gate = idx % 3;
    const float* b = (gate == 0) ? bf : (gate == 1) ? bg : bo;
    g_bias[idx] = b[h];
}

__global__ void prep_xf16(const float* __restrict__ x)
{
    size_t idx = (size_t)blockIdx.x * blockDim.x + threadIdx.x;
    if (idx >= (size_t)TT * BB * DD) return;
    int k = idx % DD;
    size_t tb = idx / DD;
    int b = tb % BB;
    int t = tb / BB;
    g_xf16[((size_t)t * BB + b) * DD + k] =
        __float2half(x[(size_t)b * (TT * DD) + (size_t)t * DD + k]);
}

__global__ void prep_X0(const float* __restrict__ x)
{
    size_t idx = (size_t)blockIdx.x * blockDim.x + threadIdx.x;
    if (idx >= (size_t)BB * KS) return;
    int k = idx % KS;
    int b = idx / KS;
    g_X[1][idx] = __float2half(0.0f);
    g_X[0][idx] = (k < DD) ? __float2half(x[(size_t)b * (TT * DD) + k]) : __float2half(0.0f);
}

__global__ void prep_czero()
{
    int idx = blockIdx.x * blockDim.x + threadIdx.x;
    if (idx < HH * BB) g_c[idx] = 0.0f;
}

__global__ void prep_igate(const float* __restrict__ latlons, const float* __restrict__ yearly,
                           const float* __restrict__ Wu, const float* __restrict__ bu)
{
    int idx = blockIdx.x * blockDim.x + threadIdx.x;
    if (idx >= HH * BB) return;
    int b = idx & (BB - 1);
    int h = idx >> 11;
    const float* w = Wu + h * SS;
    float s = bu[h];
    s += w[0] * latlons[b * 2 + 0];
    s += w[1] * latlons[b * 2 + 1];
    #pragma unroll
    for (int i = 0; i < 37; i++) s += w[2 + i] * yearly[b * 37 + i];
    g_ig[idx] = 1.0f / (1.0f + expf(-s));
}

__global__ void prep_head(const float* __restrict__ Wd0, const float* __restrict__ bd0,
                          const float* __restrict__ Wd1, const float* __restrict__ bd1)
{
    int idx = threadIdx.x;
    if (idx < HH + PMM) {
        float s = 0.0f;
        for (int m = 0; m < 256; m++) s += Wd1[m] * Wd0[m * (HH + PMM) + idx];
        g_weff[idx] = s;
    }
    if (idx == HH + PMM) {
        float s = bd1[0];
        for (int m = 0; m < 256; m++) s += Wd1[m] * bd0[m];
        g_beff = s;
    }
}

// ---------------- recurrent step (HMMA mma.sync, single-term fp16) ----------------
// CTA: 128 batch x 96 j (= 32 h x 3 gates). Grid (16, 8). 8 warps = 2m x 4n.
__global__ void __launch_bounds__(256, 1) step_kernel(int t)
{
    extern __shared__ char smem[];
    const uint32_t sb = smem_u32(smem);
    const int tid = threadIdx.x;
    const int wid = tid >> 5;
    const int lane = tid & 31;
    const int wm = wid & 1;        // 0..1 (64 rows each)
    const int wn = wid >> 1;       // 0..3 (24 cols each)
    const int bm = blockIdx.x;     // batch tile 0..15
    const int jt = blockIdx.y;     // j tile 0..7 (h group of 32)
    const int b_base = bm * 128;

    const __half* __restrict__ Xb = g_X[t & 1];

    float acc[4][3][4];
    #pragma unroll
    for (int mt = 0; mt < 4; mt++)
        #pragma unroll
        for (int nt = 0; nt < 3; nt++)
            #pragma unroll
            for (int q = 0; q < 4; q++) acc[mt][nt][q] = 0.0f;

    auto load_stage = [&](int c, int st) {
        const int kc = c * KB;
        #pragma unroll
        for (int i = 0; i < 4; i++) {
            int slot = tid + i * 256;
            int row = slot >> 3;
            int cq = slot & 7;
            const void* src = Xb + (size_t)(b_base + row) * KS + kc + cq * 8;
            cp16(sb + st * A_STAGE + row * A_PITCH + cq * 16, src);
        }
        #pragma unroll
        for (int i = 0; i < 3; i++) {
            int slot = tid + i * 256;
            int row = slot / 12;
            int cq = slot - row * 12;
            const void* src = g_W + (size_t)(kc + row) * NTOT + jt * 96 + cq * 8;
            cp16(sb + B_ORIGIN + st * B_STAGE + row * B_PITCH + cq * 16, src);
        }
        cp_commit();
    };

    const uint32_t a_off = (uint32_t)((wm * 64 + (lane & 15)) * A_PITCH + (lane >> 4) * 16);
    const uint32_t b_off = (uint32_t)((lane & 15) * B_PITCH + wn * 48);

    load_stage(0, 0);
    load_stage(1, 1);

    for (int c = 0; c < NCHUNK; c++) {
        const int st = c % NSTAGE;
        cp_wait<1>();
        __syncthreads();
        if (c + 2 < NCHUNK) load_stage(c + 2, (c + 2) % NSTAGE);
        else cp_commit();   // keep group count aligned

        uint32_t aB = sb + st * A_STAGE + a_off;
        uint32_t bB = sb + B_ORIGIN + st * B_STAGE + b_off;
        #pragma unroll
        for (int kk = 0; kk < 4; kk++) {
            uint32_t af[4][4], bf[3][2];
            #pragma unroll
            for (int mt = 0; mt < 4; mt++) ldm_x4(af[mt], aB + mt * (16 * A_PITCH) + kk * 32);
            #pragma unroll
            for (int nt = 0; nt < 3; nt++) ldm_x2t(bf[nt], bB + kk * (16 * B_PITCH) + nt * 16);
            #pragma unroll
            for (int mt = 0; mt < 4; mt++)
                #pragma unroll
                for (int nt = 0; nt < 3; nt++)
                    mma16816(acc[mt][nt], af[mt], bf[nt]);
        }
    }
    __syncthreads();

    // ---- dump accumulators to smem C [128][C_PITCH] fp32 (overlaps dead stages) ----
    float* Cs = (float*)smem;
    {
        const int r0 = wm * 64 + (lane >> 2);
        const int c0 = wn * 24 + (lane & 3) * 2;
        #pragma unroll
        for (int mt = 0; mt < 4; mt++)
            #pragma unroll
            for (int nt = 0; nt < 3; nt++) {
                int r = r0 + mt * 16;
                int cc = c0 + nt * 8;
                Cs[r * C_PITCH + cc]           = acc[mt][nt][0];
                Cs[r * C_PITCH + cc + 1]       = acc[mt][nt][1];
                Cs[(r + 8) * C_PITCH + cc]     = acc[mt][nt][2];
                Cs[(r + 8) * C_PITCH + cc + 1] = acc[mt][nt][3];
            }
    }
    __syncthreads();

    // ---- gates + state update ----
    uint32_t* Hs = (uint32_t*)(smem + HS_ORIGIN);   // [32][HS_PITCH], h value as fp16 in low bits
    #pragma unroll
    for (int i = 0; i < 16; i++) {
        int idx = i * 256 + tid;
        int b_l = idx & 127;
        int h_l = idx >> 7;
        int hg = jt * 32 + h_l;
        float fp = Cs[b_l * C_PITCH + h_l * 3 + 0] + g_bias[hg * 3 + 0];
        float gp = Cs[b_l * C_PITCH + h_l * 3 + 1] + g_bias[hg * 3 + 1];
        float op = Cs[b_l * C_PITCH + h_l * 3 + 2] + g_bias[hg * 3 + 2];
        float f = 1.0f / (1.0f + expf(-fp));
        float g = tanhf(gp);
        float o = 1.0f / (1.0f + expf(-op));
        size_t off = (size_t)hg * BB + b_base + b_l;
        float c1 = f * g_c[off] + g_ig[off] * g;
        g_c[off] = c1;
        float hv = o * tanhf(c1);
        __half hi = __float2half(hv);
        Hs[h_l * HS_PITCH + b_l] = (uint32_t)*(uint16_t*)&hi;
    }
    __syncthreads();

    // ---- write h into next X buffer ----
    if (tid < 128) {
        const int b = b_base + tid;
        __half* Xo = &g_X[(t + 1) & 1][(size_t)b * KS];
        const int h0 = jt * 32;
        #pragma unroll
        for (int i = 0; i < 4; i++) {          // 4 x 8 h values
            uint4 vh;
            uint32_t* ph = (uint32_t*)&vh;
            #pragma unroll
            for (int q = 0; q < 4; q++) {
                uint32_t p0 = Hs[(i * 8 + q * 2) * HS_PITCH + tid];
                uint32_t p1 = Hs[(i * 8 + q * 2 + 1) * HS_PITCH + tid];
                ph[q] = p0 | (p1 << 16);
            }
            *(uint4*)(Xo + 32 + h0 + i * 8) = vh;
        }
        if (jt == 0 && t < TT - 1) {
            const __half* xs = g_xf16 + ((size_t)(t + 1) * BB + b) * DD;
            #pragma unroll
            for (int i = 0; i < 4; i++)
                *(uint4*)(Xo + i * 8) = *(const uint4*)(xs + i * 8);
        }
    }
}

// ---------------- head ----------------
__global__ void head_kernel(const float* __restrict__ pm, float* __restrict__ out)
{
    int b = blockIdx.x * blockDim.x + threadIdx.x;
    if (b >= BB) return;
    const __half* Xrow = &g_X[0][(size_t)b * KS];   // T=128 even -> final h in buffer 0
    float s = g_beff;
    #pragma unroll 8
    for (int k = 0; k < HH; k++)
        s += __half2float(Xrow[32 + k]) * g_weff[k];
    #pragma unroll
    for (int k = 0; k < PMM; k++) s += pm[b * PMM + k] * g_weff[HH + k];
    out[b] = s;
}

// ---------------- launch ----------------
extern "C" void kernel_launch(void* const* d_in, const int* in_sizes, int n_in,
                              void* d_out, int out_size)
{
    const float* x       = (const float*)d_in[0];
    const float* latlons = (const float*)d_in[1];
    const float* yearly  = (const float*)d_in[2];
    const float* pm      = (const float*)d_in[3];
    const float* Wf_i    = (const float*)d_in[4];
    const float* Wf_h    = (const float*)d_in[5];
    const float* bf      = (const float*)d_in[6];
    const float* Wu      = (const float*)d_in[7];
    const float* bu      = (const float*)d_in[8];
    const float* Wg_i    = (const float*)d_in[9];
    const float* Wg_h    = (const float*)d_in[10];
    const float* bg      = (const float*)d_in[11];
    const float* Wo_i    = (const float*)d_in[12];
    const float* Wo_h    = (const float*)d_in[13];
    const float* bo      = (const float*)d_in[14];
    const float* Wd0     = (const float*)d_in[15];
    const float* bd0     = (const float*)d_in[16];
    const float* Wd1     = (const float*)d_in[17];
    const float* bd1     = (const float*)d_in[18];

    static bool attr_set = false;
    if (!attr_set) {
        cudaFuncSetAttribute(step_kernel, cudaFuncAttributeMaxDynamicSharedMemorySize, SMEM_TOTAL);
        attr_set = true;
    }

    prep_W<<<(KS * NTOT + 255) / 256, 256>>>(Wf_i, Wf_h, Wg_i, Wg_h, Wo_i, Wo_h);
    prep_bias<<<3, 256>>>(bf, bg, bo);
    prep_xf16<<<(int)(((size_t)TT * BB * DD + 255) / 256), 256>>>(x);
    prep_X0<<<(int)(((size_t)BB * KS + 255) / 256), 256>>>(x);
    prep_czero<<<(HH * BB + 255) / 256, 256>>>();
    prep_igate<<<(HH * BB + 255) / 256, 256>>>(latlons, yearly, Wu, bu);
    prep_head<<<1, 512>>>(Wd0, bd0, Wd1, bd1);

    for (int t = 0; t < TT; t++) {
        step_kernel<<<dim3(16, 8), 256, SMEM_TOTAL>>>(t);
    }

    head_kernel<<<(BB + 255) / 256, 256>>>(pm, (float*)d_out);
}

// round 6
// speedup vs baseline: 3.0284x; 1.5198x over previous
#include <cuda_runtime.h>
#include <cuda_fp16.h>
#include <math.h>
#include <stdint.h>

#define BB 2048
#define TT 128
#define DD 32
#define HH 256
#define SS 39
#define PMM 12
#define KR 288              /* k layout: [h 256 | x 32] */
#define NTOT 768            /* j = h*3 + gate */
#define KB 96
#define NCHUNK 3
#define NK16 18             /* 288/16 */

/* smem layout (bytes) */
#define A_PITCH 208                       /* 104 halfs: 96 data + 8 pad, odd x 16B */
#define A_STAGE (128 * A_PITCH)           /* 26624 */
#define W_ORIGIN (3 * A_STAGE)            /* 79872 */
#define W_PITCH 208
#define C_PITCH 101                       /* fp32 words per row */
#define HS_ORIGIN 52224                   /* inside A ring, after C (51712) */
#define HS_PITCH 129                      /* uint32 per row */
#define CELL_ORIGIN (W_ORIGIN + KR * W_PITCH)   /* 139776 */
#define IG_ORIGIN (CELL_ORIGIN + 16384)         /* 156160 */
#define SMEM_TOTAL (IG_ORIGIN + 16384)          /* 172544 */

// ---------------- device scratch ----------------
__device__ __half g_X[2][BB * KR];               // activations [b][k], ping-pong
__device__ __half g_W[KR * NTOT];                // weights [k][j]
__device__ __half g_xf16[(size_t)TT * BB * DD];  // per-t x fp16: [t][b][32]
__device__ float g_bias[NTOT];                   // interleaved [h*3+gate]
__device__ float g_ig[HH * BB];                  // input gate [h][b]
__device__ float g_weff[HH + PMM];
__device__ float g_beff;
__device__ unsigned int g_bar_cnt;
__device__ volatile unsigned int g_bar_phase;

// ---------------- asm helpers ----------------
__device__ __forceinline__ uint32_t smem_u32(const void* p) {
    uint32_t a;
    asm("{ .reg .u64 t; cvta.to.shared.u64 t, %1; cvt.u32.u64 %0, t; }" : "=r"(a) : "l"(p));
    return a;
}
__device__ __forceinline__ void cp16(uint32_t dst, const void* src) {
    asm volatile("cp.async.cg.shared.global [%0], [%1], 16;" :: "r"(dst), "l"(src) : "memory");
}
__device__ __forceinline__ void cp_commit() {
    asm volatile("cp.async.commit_group;" ::: "memory");
}
template <int N>
__device__ __forceinline__ void cp_wait() {
    asm volatile("cp.async.wait_group %0;" :: "n"(N) : "memory");
}
__device__ __forceinline__ void ldm_x4(uint32_t* r, uint32_t addr) {
    asm volatile("ldmatrix.sync.aligned.m8n8.x4.shared.b16 {%0,%1,%2,%3}, [%4];"
                 : "=r"(r[0]), "=r"(r[1]), "=r"(r[2]), "=r"(r[3]) : "r"(addr));
}
__device__ __forceinline__ void ldm_x2t(uint32_t* r, uint32_t addr) {
    asm volatile("ldmatrix.sync.aligned.m8n8.x2.trans.shared.b16 {%0,%1}, [%2];"
                 : "=r"(r[0]), "=r"(r[1]) : "r"(addr));
}
__device__ __forceinline__ void mma16816(float* d, const uint32_t* a, const uint32_t* b) {
    asm volatile(
        "mma.sync.aligned.m16n8k16.row.col.f32.f16.f16.f32 "
        "{%0,%1,%2,%3}, {%4,%5,%6,%7}, {%8,%9}, {%0,%1,%2,%3};"
        : "+f"(d[0]), "+f"(d[1]), "+f"(d[2]), "+f"(d[3])
        : "r"(a[0]), "r"(a[1]), "r"(a[2]), "r"(a[3]), "r"(b[0]), "r"(b[1]));
}

// ---------------- prep kernels ----------------
__global__ void prep_W(const float* __restrict__ Wf_i, const float* __restrict__ Wf_h,
                       const float* __restrict__ Wg_i, const float* __restrict__ Wg_h,
                       const float* __restrict__ Wo_i, const float* __restrict__ Wo_h)
{
    int idx = blockIdx.x * blockDim.x + threadIdx.x;
    if (idx >= KR * NTOT) return;
    int k = idx / NTOT;
    int j = idx - k * NTOT;
    int h = j / 3, gate = j % 3;
    const float* Wi = (gate == 0) ? Wf_i : (gate == 1) ? Wg_i : Wo_i;
    const float* Wh = (gate == 0) ? Wf_h : (gate == 1) ? Wg_h : Wo_h;
    float w = (k < HH) ? Wh[h * HH + k] : Wi[h * DD + (k - HH)];
    g_W[idx] = __float2half(w);
}

__global__ void prep_bias(const float* __restrict__ bf, const float* __restrict__ bg, const float* __restrict__ bo)
{
    int idx = blockIdx.x * blockDim.x + threadIdx.x;
    if (idx >= NTOT) return;
    int h = idx / 3, gate = idx % 3;
    const float* b = (gate == 0) ? bf : (gate == 1) ? bg : bo;
    g_bias[idx] = b[h];
}

__global__ void prep_xf16(const float* __restrict__ x)
{
    size_t idx = (size_t)blockIdx.x * blockDim.x + threadIdx.x;
    if (idx >= (size_t)TT * BB * DD) return;
    int k = idx % DD;
    size_t tb = idx / DD;
    int b = tb % BB;
    int t = tb / BB;
    g_xf16[((size_t)t * BB + b) * DD + k] =
        __float2half(x[(size_t)b * (TT * DD) + (size_t)t * DD + k]);
}

__global__ void prep_X0(const float* __restrict__ x)
{
    size_t idx = (size_t)blockIdx.x * blockDim.x + threadIdx.x;
    if (idx >= (size_t)BB * KR) return;
    int k = idx % KR;
    int b = idx / KR;
    g_X[1][idx] = __float2half(0.0f);
    g_X[0][idx] = (k >= HH) ? __float2half(x[(size_t)b * (TT * DD) + (k - HH)]) : __float2half(0.0f);
}

__global__ void prep_igate(const float* __restrict__ latlons, const float* __restrict__ yearly,
                           const float* __restrict__ Wu, const float* __restrict__ bu)
{
    int idx = blockIdx.x * blockDim.x + threadIdx.x;
    if (idx >= HH * BB) return;
    int b = idx & (BB - 1);
    int h = idx >> 11;
    const float* w = Wu + h * SS;
    float s = bu[h];
    s += w[0] * latlons[b * 2 + 0];
    s += w[1] * latlons[b * 2 + 1];
    #pragma unroll
    for (int i = 0; i < 37; i++) s += w[2 + i] * yearly[b * 37 + i];
    g_ig[idx] = 1.0f / (1.0f + expf(-s));
}

__global__ void prep_head(const float* __restrict__ Wd0, const float* __restrict__ bd0,
                          const float* __restrict__ Wd1, const float* __restrict__ bd1)
{
    int idx = threadIdx.x;
    if (idx < HH + PMM) {
        float s = 0.0f;
        for (int m = 0; m < 256; m++) s += Wd1[m] * Wd0[m * (HH + PMM) + idx];
        g_weff[idx] = s;
    }
    if (idx == HH + PMM) {
        float s = bd1[0];
        for (int m = 0; m < 256; m++) s += Wd1[m] * bd0[m];
        g_beff = s;
    }
    if (idx == HH + PMM + 1) { g_bar_cnt = 0; g_bar_phase = 0; }
}

// ---------------- persistent recurrent kernel ----------------
// 128 CTAs (16 bm x 8 jt), 1 CTA/SM, all co-resident. Grid barrier between steps.
__global__ void __launch_bounds__(256, 1) step_persist()
{
    extern __shared__ char smem[];
    const uint32_t sb = smem_u32(smem);
    const int tid = threadIdx.x;
    const int wid = tid >> 5;
    const int lane = tid & 31;
    const int wm = wid & 1;
    const int wn = wid >> 1;
    const int bm = blockIdx.x;     // 0..15
    const int jt = blockIdx.y;     // 0..7
    const int b_base = bm * 128;
    const int h0 = jt * 32;

    float* c_s = (float*)(smem + CELL_ORIGIN);    // [32][128]
    float* ig_s = (float*)(smem + IG_ORIGIN);     // [32][128]
    float* Cs = (float*)smem;                     // [128][C_PITCH] (overlaps A ring)
    uint32_t* Hs = (uint32_t*)(smem + HS_ORIGIN); // [32][HS_PITCH]

    // ---- prologue: W tile -> SMEM (once) ----
    #pragma unroll
    for (int i = 0; i < 14; i++) {
        int slot = tid + i * 256;
        if (slot < KR * 12) {
            int row = slot / 12;
            int cq = slot - row * 12;
            cp16(sb + W_ORIGIN + row * W_PITCH + cq * 16,
                 g_W + (size_t)row * NTOT + jt * 96 + cq * 8);
        }
    }
    cp_commit();

    // ---- prologue: ig -> SMEM, c = 0 ----
    #pragma unroll
    for (int i = 0; i < 16; i++) {
        int idx = i * 256 + tid;
        int b_l = idx & 127;
        int h_l = idx >> 7;
        ig_s[h_l * 128 + b_l] = g_ig[(size_t)(h0 + h_l) * BB + b_base + b_l];
        c_s[h_l * 128 + b_l] = 0.0f;
    }
    cp_wait<0>();
    __syncthreads();

    // ---- hoist W fragments into registers (for all 18 k16 steps) ----
    uint32_t bfrag[NK16][3][2];
    {
        const uint32_t wb = sb + W_ORIGIN + (lane & 15) * W_PITCH + wn * 48;
        #pragma unroll
        for (int k16 = 0; k16 < NK16; k16++)
            #pragma unroll
            for (int nt = 0; nt < 3; nt++)
                ldm_x2t(bfrag[k16][nt], wb + k16 * (16 * W_PITCH) + nt * 16);
    }
    __syncthreads();

    const uint32_t a_off = (uint32_t)((wm * 64 + (lane & 15)) * A_PITCH + (lane >> 4) * 16);

    for (int t = 0; t < TT; t++) {
        const __half* __restrict__ Xb = g_X[t & 1];

        // ---- issue all 3 A chunks (cp.async.cg: L2-only, no stale L1) ----
        #pragma unroll
        for (int c = 0; c < NCHUNK; c++) {
            #pragma unroll
            for (int i = 0; i < 6; i++) {
                int slot = tid + i * 256;
                int row = slot / 12;
                int cq = slot - row * 12;
                cp16(sb + c * A_STAGE + row * A_PITCH + cq * 16,
                     Xb + (size_t)(b_base + row) * KR + c * 96 + cq * 8);
            }
            cp_commit();
        }

        float acc[4][3][4];
        #pragma unroll
        for (int mt = 0; mt < 4; mt++)
            #pragma unroll
            for (int nt = 0; nt < 3; nt++)
                #pragma unroll
                for (int q = 0; q < 4; q++) acc[mt][nt][q] = 0.0f;

        // ---- MMA over 3 chunks x 6 k16 ----
        #pragma unroll
        for (int c = 0; c < NCHUNK; c++) {
            if (c == 0) cp_wait<2>();
            else if (c == 1) cp_wait<1>();
            else cp_wait<0>();
            __syncthreads();
            const uint32_t aB = sb + c * A_STAGE + a_off;
            #pragma unroll
            for (int kk = 0; kk < 6; kk++) {
                uint32_t af[4][4];
                #pragma unroll
                for (int mt = 0; mt < 4; mt++)
                    ldm_x4(af[mt], aB + mt * (16 * A_PITCH) + kk * 32);
                #pragma unroll
                for (int mt = 0; mt < 4; mt++)
                    #pragma unroll
                    for (int nt = 0; nt < 3; nt++)
                        mma16816(acc[mt][nt], af[mt], bfrag[c * 6 + kk][nt]);
            }
        }
        __syncthreads();

        // ---- dump accumulators to C scratch ----
        {
            const int r0 = wm * 64 + (lane >> 2);
            const int c0 = wn * 24 + (lane & 3) * 2;
            #pragma unroll
            for (int mt = 0; mt < 4; mt++)
                #pragma unroll
                for (int nt = 0; nt < 3; nt++) {
                    int r = r0 + mt * 16;
                    int cc = c0 + nt * 8;
                    Cs[r * C_PITCH + cc]           = acc[mt][nt][0];
                    Cs[r * C_PITCH + cc + 1]       = acc[mt][nt][1];
                    Cs[(r + 8) * C_PITCH + cc]     = acc[mt][nt][2];
                    Cs[(r + 8) * C_PITCH + cc + 1] = acc[mt][nt][3];
                }
        }
        __syncthreads();

        // ---- gates + state update (c, ig resident in SMEM) ----
        #pragma unroll
        for (int i = 0; i < 16; i++) {
            int idx = i * 256 + tid;
            int b_l = idx & 127;
            int h_l = idx >> 7;
            int hg = h0 + h_l;
            float fp = Cs[b_l * C_PITCH + h_l * 3 + 0] + g_bias[hg * 3 + 0];
            float gp = Cs[b_l * C_PITCH + h_l * 3 + 1] + g_bias[hg * 3 + 1];
            float op = Cs[b_l * C_PITCH + h_l * 3 + 2] + g_bias[hg * 3 + 2];
            float f = __fdividef(1.0f, 1.0f + __expf(-fp));
            float g = __fdividef(2.0f, 1.0f + __expf(-2.0f * gp)) - 1.0f;
            float o = __fdividef(1.0f, 1.0f + __expf(-op));
            int off = h_l * 128 + b_l;
            float c1 = f * c_s[off] + ig_s[off] * g;
            c_s[off] = c1;
            float th = __fdividef(2.0f, 1.0f + __expf(-2.0f * c1)) - 1.0f;
            float hv = o * th;
            __half hh = __float2half(hv);
            Hs[h_l * HS_PITCH + b_l] = (uint32_t)*(uint16_t*)&hh;
        }
        __syncthreads();

        // ---- write h (and next x for jt==0) into next X buffer ----
        if (tid < 128) {
            const int b = b_base + tid;
            __half* Xo = &g_X[(t + 1) & 1][(size_t)b * KR];
            #pragma unroll
            for (int i = 0; i < 4; i++) {
                uint4 vh;
                uint32_t* ph = (uint32_t*)&vh;
                #pragma unroll
                for (int q = 0; q < 4; q++) {
                    uint32_t p0 = Hs[(i * 8 + q * 2) * HS_PITCH + tid];
                    uint32_t p1 = Hs[(i * 8 + q * 2 + 1) * HS_PITCH + tid];
                    ph[q] = p0 | (p1 << 16);
                }
                *(uint4*)(Xo + h0 + i * 8) = vh;
            }
            if (jt == 0 && t < TT - 1) {
                const __half* xs = g_xf16 + ((size_t)(t + 1) * BB + b) * DD;
                #pragma unroll
                for (int i = 0; i < 4; i++)
                    *(uint4*)(Xo + HH + i * 8) = *(const uint4*)(xs + i * 8);
            }
        }

        // ---- grid barrier ----
        if (t < TT - 1) {
            __syncthreads();
            if (tid == 0) {
                __threadfence();
                unsigned int v = atomicAdd(&g_bar_cnt, 1);
                unsigned int target = (unsigned int)(t + 1);
                if (v == 127) {
                    g_bar_cnt = 0;
                    __threadfence();
                    g_bar_phase = target;
                } else {
                    while (g_bar_phase < target) {}
                    __threadfence();
                }
            }
            __syncthreads();
        }
    }
}

// ---------------- head ----------------
__global__ void head_kernel(const float* __restrict__ pm, float* __restrict__ out)
{
    int b = blockIdx.x * blockDim.x + threadIdx.x;
    if (b >= BB) return;
    const __half* Xrow = &g_X[0][(size_t)b * KR];   // T=128 even -> final h in buffer 0
    float s = g_beff;
    #pragma unroll 8
    for (int k = 0; k < HH; k++)
        s += __half2float(Xrow[k]) * g_weff[k];
    #pragma unroll
    for (int k = 0; k < PMM; k++) s += pm[b * PMM + k] * g_weff[HH + k];
    out[b] = s;
}

// ---------------- launch ----------------
extern "C" void kernel_launch(void* const* d_in, const int* in_sizes, int n_in,
                              void* d_out, int out_size)
{
    const float* x       = (const float*)d_in[0];
    const float* latlons = (const float*)d_in[1];
    const float* yearly  = (const float*)d_in[2];
    const float* pm      = (const float*)d_in[3];
    const float* Wf_i    = (const float*)d_in[4];
    const float* Wf_h    = (const float*)d_in[5];
    const float* bf      = (const float*)d_in[6];
    const float* Wu      = (const float*)d_in[7];
    const float* bu      = (const float*)d_in[8];
    const float* Wg_i    = (const float*)d_in[9];
    const float* Wg_h    = (const float*)d_in[10];
    const float* bg      = (const float*)d_in[11];
    const float* Wo_i    = (const float*)d_in[12];
    const float* Wo_h    = (const float*)d_in[13];
    const float* bo      = (const float*)d_in[14];
    const float* Wd0     = (const float*)d_in[15];
    const float* bd0     = (const float*)d_in[16];
    const float* Wd1     = (const float*)d_in[17];
    const float* bd1     = (const float*)d_in[18];

    static bool attr_set = false;
    if (!attr_set) {
        cudaFuncSetAttribute(step_persist, cudaFuncAttributeMaxDynamicSharedMemorySize, SMEM_TOTAL);
        attr_set = true;
    }

    prep_W<<<(KR * NTOT + 255) / 256, 256>>>(Wf_i, Wf_h, Wg_i, Wg_h, Wo_i, Wo_h);
    prep_bias<<<3, 256>>>(bf, bg, bo);
    prep_xf16<<<(int)(((size_t)TT * BB * DD + 255) / 256), 256>>>(x);
    prep_X0<<<(int)(((size_t)BB * KR + 255) / 256), 256>>>(x);
    prep_igate<<<(HH * BB + 255) / 256, 256>>>(latlons, yearly, Wu, bu);
    prep_head<<<1, 512>>>(Wd0, bd0, Wd1, bd1);

    step_persist<<<dim3(16, 8), 256, SMEM_TOTAL>>>();

    head_kernel<<<(BB + 255) / 256, 256>>>(pm, (float*)d_out);
}

// round 7
// speedup vs baseline: 3.4620x; 1.1432x over previous
#include <cuda_runtime.h>
#include <cuda_fp16.h>
#include <math.h>
#include <stdint.h>

#define BB 2048
#define TT 128
#define DD 32
#define HH 256
#define SS 39
#define PMM 12
#define KR 288              /* k layout: [h 256 | x 32] */
#define NTOT 768            /* j = h*3 + gate */
#define NCHUNK 3
#define NK16 18             /* 288/16 */

/* smem layout (bytes) */
#define A_PITCH 208                       /* 104 halfs: 96 data + 8 pad, odd x 16B */
#define A_STAGE (128 * A_PITCH)           /* 26624 */
#define W_ORIGIN (3 * A_STAGE)            /* 79872 */
#define W_PITCH 208
#define C_PITCH 101                       /* fp32 words per row */
#define HS_ORIGIN 52224                   /* inside A ring, after C (51712) */
#define HS_PITCH 129                      /* uint32 per row */
#define CELL_ORIGIN (W_ORIGIN + KR * W_PITCH)   /* 139776 */
#define IG_ORIGIN (CELL_ORIGIN + 16384)         /* 156160 */
#define SMEM_TOTAL (IG_ORIGIN + 16384)          /* 172544 */

// ---------------- device scratch ----------------
__device__ __half g_X[2][BB * KR];               // activations [b][k], ping-pong
__device__ __half g_W[KR * NTOT];                // weights [k][j]
__device__ __half g_xf16[(size_t)TT * BB * DD];  // per-t x fp16: [t][b][32]
__device__ float g_bias[NTOT];                   // interleaved [h*3+gate]
__device__ float g_ig[HH * BB];                  // input gate [h][b]
__device__ float g_weff[HH + PMM];
__device__ float g_beff;
__device__ unsigned int g_cnt[16 * 32];                 // per-bm barrier counters (128B apart)
__device__ volatile unsigned int g_phase[16 * 32];      // per-bm barrier phase

// ---------------- asm helpers ----------------
__device__ __forceinline__ uint32_t smem_u32(const void* p) {
    uint32_t a;
    asm("{ .reg .u64 t; cvta.to.shared.u64 t, %1; cvt.u32.u64 %0, t; }" : "=r"(a) : "l"(p));
    return a;
}
__device__ __forceinline__ void cp16(uint32_t dst, const void* src) {
    asm volatile("cp.async.cg.shared.global [%0], [%1], 16;" :: "r"(dst), "l"(src) : "memory");
}
__device__ __forceinline__ void cp_commit() {
    asm volatile("cp.async.commit_group;" ::: "memory");
}
template <int N>
__device__ __forceinline__ void cp_wait() {
    asm volatile("cp.async.wait_group %0;" :: "n"(N) : "memory");
}
__device__ __forceinline__ void ldm_x4(uint32_t* r, uint32_t addr) {
    asm volatile("ldmatrix.sync.aligned.m8n8.x4.shared.b16 {%0,%1,%2,%3}, [%4];"
                 : "=r"(r[0]), "=r"(r[1]), "=r"(r[2]), "=r"(r[3]) : "r"(addr));
}
__device__ __forceinline__ void ldm_x2t(uint32_t* r, uint32_t addr) {
    asm volatile("ldmatrix.sync.aligned.m8n8.x2.trans.shared.b16 {%0,%1}, [%2];"
                 : "=r"(r[0]), "=r"(r[1]) : "r"(addr));
}
__device__ __forceinline__ void mma16816(float* d, const uint32_t* a, const uint32_t* b) {
    asm volatile(
        "mma.sync.aligned.m16n8k16.row.col.f32.f16.f16.f32 "
        "{%0,%1,%2,%3}, {%4,%5,%6,%7}, {%8,%9}, {%0,%1,%2,%3};"
        : "+f"(d[0]), "+f"(d[1]), "+f"(d[2]), "+f"(d[3])
        : "r"(a[0]), "r"(a[1]), "r"(a[2]), "r"(a[3]), "r"(b[0]), "r"(b[1]));
}
__device__ __forceinline__ float tanh_fast(float x) {
    float y;
    asm("tanh.approx.f32 %0, %1;" : "=f"(y) : "f"(x));
    return y;
}
__device__ __forceinline__ float sigmoid_fast(float x) {
    return fmaf(0.5f, tanh_fast(0.5f * x), 0.5f);
}

// ---------------- prep kernels ----------------
__global__ void prep_W(const float* __restrict__ Wf_i, const float* __restrict__ Wf_h,
                       const float* __restrict__ Wg_i, const float* __restrict__ Wg_h,
                       const float* __restrict__ Wo_i, const float* __restrict__ Wo_h)
{
    int idx = blockIdx.x * blockDim.x + threadIdx.x;
    if (idx >= KR * NTOT) return;
    int k = idx / NTOT;
    int j = idx - k * NTOT;
    int h = j / 3, gate = j % 3;
    const float* Wi = (gate == 0) ? Wf_i : (gate == 1) ? Wg_i : Wo_i;
    const float* Wh = (gate == 0) ? Wf_h : (gate == 1) ? Wg_h : Wo_h;
    float w = (k < HH) ? Wh[h * HH + k] : Wi[h * DD + (k - HH)];
    g_W[idx] = __float2half(w);
}

__global__ void prep_bias(const float* __restrict__ bf, const float* __restrict__ bg, const float* __restrict__ bo)
{
    int idx = blockIdx.x * blockDim.x + threadIdx.x;
    if (idx >= NTOT) return;
    int h = idx / 3, gate = idx % 3;
    const float* b = (gate == 0) ? bf : (gate == 1) ? bg : bo;
    g_bias[idx] = b[h];
}

__global__ void prep_xf16(const float* __restrict__ x)
{
    size_t idx = (size_t)blockIdx.x * blockDim.x + threadIdx.x;
    if (idx >= (size_t)TT * BB * DD) return;
    int k = idx % DD;
    size_t tb = idx / DD;
    int b = tb % BB;
    int t = tb / BB;
    g_xf16[((size_t)t * BB + b) * DD + k] =
        __float2half(x[(size_t)b * (TT * DD) + (size_t)t * DD + k]);
}

__global__ void prep_X0(const float* __restrict__ x)
{
    size_t idx = (size_t)blockIdx.x * blockDim.x + threadIdx.x;
    if (idx >= (size_t)BB * KR) return;
    int k = idx % KR;
    int b = idx / KR;
    g_X[1][idx] = __float2half(0.0f);
    g_X[0][idx] = (k >= HH) ? __float2half(x[(size_t)b * (TT * DD) + (k - HH)]) : __float2half(0.0f);
}

__global__ void prep_igate(const float* __restrict__ latlons, const float* __restrict__ yearly,
                           const float* __restrict__ Wu, const float* __restrict__ bu)
{
    int idx = blockIdx.x * blockDim.x + threadIdx.x;
    if (idx >= HH * BB) return;
    int b = idx & (BB - 1);
    int h = idx >> 11;
    const float* w = Wu + h * SS;
    float s = bu[h];
    s += w[0] * latlons[b * 2 + 0];
    s += w[1] * latlons[b * 2 + 1];
    #pragma unroll
    for (int i = 0; i < 37; i++) s += w[2 + i] * yearly[b * 37 + i];
    g_ig[idx] = 1.0f / (1.0f + expf(-s));
}

__global__ void prep_head(const float* __restrict__ Wd0, const float* __restrict__ bd0,
                          const float* __restrict__ Wd1, const float* __restrict__ bd1)
{
    int idx = threadIdx.x;
    if (idx < HH + PMM) {
        float s = 0.0f;
        for (int m = 0; m < 256; m++) s += Wd1[m] * Wd0[m * (HH + PMM) + idx];
        g_weff[idx] = s;
    }
    if (idx == HH + PMM) {
        float s = bd1[0];
        for (int m = 0; m < 256; m++) s += Wd1[m] * bd0[m];
        g_beff = s;
    }
    if (idx >= 384 && idx < 400) {
        g_cnt[(idx - 384) * 32] = 0;
        g_phase[(idx - 384) * 32] = 0;
    }
}

// ---------------- persistent recurrent kernel ----------------
// 128 CTAs (16 bm x 8 jt), 1 CTA/SM. Per-bm 8-CTA barrier between steps.
__global__ void __launch_bounds__(256, 1) step_persist()
{
    extern __shared__ char smem[];
    const uint32_t sb = smem_u32(smem);
    const int tid = threadIdx.x;
    const int wid = tid >> 5;
    const int lane = tid & 31;
    const int wm = wid & 1;
    const int wn = wid >> 1;
    const int bm = blockIdx.x;     // 0..15
    const int jt = blockIdx.y;     // 0..7
    const int b_base = bm * 128;
    const int h0 = jt * 32;

    float* c_s = (float*)(smem + CELL_ORIGIN);    // [32][128]
    float* ig_s = (float*)(smem + IG_ORIGIN);     // [32][128]
    float* Cs = (float*)smem;                     // [128][C_PITCH] (overlaps A ring)
    uint32_t* Hs = (uint32_t*)(smem + HS_ORIGIN); // [32][HS_PITCH]

    // ---- prologue: W tile -> SMEM (once) ----
    #pragma unroll
    for (int i = 0; i < 14; i++) {
        int slot = tid + i * 256;
        if (slot < KR * 12) {
            int row = slot / 12;
            int cq = slot - row * 12;
            cp16(sb + W_ORIGIN + row * W_PITCH + cq * 16,
                 g_W + (size_t)row * NTOT + jt * 96 + cq * 8);
        }
    }
    cp_commit();

    // ---- prologue: ig -> SMEM, c = 0 ----
    #pragma unroll
    for (int i = 0; i < 16; i++) {
        int idx = i * 256 + tid;
        int b_l = idx & 127;
        int h_l = idx >> 7;
        ig_s[h_l * 128 + b_l] = g_ig[(size_t)(h0 + h_l) * BB + b_base + b_l];
        c_s[h_l * 128 + b_l] = 0.0f;
    }
    cp_wait<0>();
    __syncthreads();

    // ---- hoist W fragments into registers ----
    uint32_t bfrag[NK16][3][2];
    {
        const uint32_t wb = sb + W_ORIGIN + (lane & 15) * W_PITCH + wn * 48;
        #pragma unroll
        for (int k16 = 0; k16 < NK16; k16++)
            #pragma unroll
            for (int nt = 0; nt < 3; nt++)
                ldm_x2t(bfrag[k16][nt], wb + k16 * (16 * W_PITCH) + nt * 16);
    }
    __syncthreads();

    const uint32_t a_off = (uint32_t)((wm * 64 + (lane & 15)) * A_PITCH + (lane >> 4) * 16);

    for (int t = 0; t < TT; t++) {
        const __half* __restrict__ Xb = g_X[t & 1];

        // ---- issue all 3 A chunks (cp.async.cg: L2-only) ----
        #pragma unroll
        for (int c = 0; c < NCHUNK; c++) {
            #pragma unroll
            for (int i = 0; i < 6; i++) {
                int slot = tid + i * 256;
                int row = slot / 12;
                int cq = slot - row * 12;
                cp16(sb + c * A_STAGE + row * A_PITCH + cq * 16,
                     Xb + (size_t)(b_base + row) * KR + c * 96 + cq * 8);
            }
            cp_commit();
        }

        float acc[4][3][4];
        #pragma unroll
        for (int mt = 0; mt < 4; mt++)
            #pragma unroll
            for (int nt = 0; nt < 3; nt++)
                #pragma unroll
                for (int q = 0; q < 4; q++) acc[mt][nt][q] = 0.0f;

        // ---- MMA over 3 chunks x 6 k16 ----
        #pragma unroll
        for (int c = 0; c < NCHUNK; c++) {
            if (c == 0) cp_wait<2>();
            else if (c == 1) cp_wait<1>();
            else cp_wait<0>();
            __syncthreads();
            const uint32_t aB = sb + c * A_STAGE + a_off;
            #pragma unroll
            for (int kk = 0; kk < 6; kk++) {
                uint32_t af[4][4];
                #pragma unroll
                for (int mt = 0; mt < 4; mt++)
                    ldm_x4(af[mt], aB + mt * (16 * A_PITCH) + kk * 32);
                #pragma unroll
                for (int mt = 0; mt < 4; mt++)
                    #pragma unroll
                    for (int nt = 0; nt < 3; nt++)
                        mma16816(acc[mt][nt], af[mt], bfrag[c * 6 + kk][nt]);
            }
        }
        __syncthreads();

        // ---- dump accumulators to C scratch ----
        {
            const int r0 = wm * 64 + (lane >> 2);
            const int c0 = wn * 24 + (lane & 3) * 2;
            #pragma unroll
            for (int mt = 0; mt < 4; mt++)
                #pragma unroll
                for (int nt = 0; nt < 3; nt++) {
                    int r = r0 + mt * 16;
                    int cc = c0 + nt * 8;
                    Cs[r * C_PITCH + cc]           = acc[mt][nt][0];
                    Cs[r * C_PITCH + cc + 1]       = acc[mt][nt][1];
                    Cs[(r + 8) * C_PITCH + cc]     = acc[mt][nt][2];
                    Cs[(r + 8) * C_PITCH + cc + 1] = acc[mt][nt][3];
                }
        }
        __syncthreads();

        // ---- gates + state update (tanh.approx; c, ig in SMEM) ----
        #pragma unroll
        for (int i = 0; i < 16; i++) {
            int idx = i * 256 + tid;
            int b_l = idx & 127;
            int h_l = idx >> 7;
            int hg = h0 + h_l;
            float fp = Cs[b_l * C_PITCH + h_l * 3 + 0] + g_bias[hg * 3 + 0];
            float gp = Cs[b_l * C_PITCH + h_l * 3 + 1] + g_bias[hg * 3 + 1];
            float op = Cs[b_l * C_PITCH + h_l * 3 + 2] + g_bias[hg * 3 + 2];
            float f = sigmoid_fast(fp);
            float g = tanh_fast(gp);
            float o = sigmoid_fast(op);
            int off = h_l * 128 + b_l;
            float c1 = f * c_s[off] + ig_s[off] * g;
            c_s[off] = c1;
            float hv = o * tanh_fast(c1);
            __half hh = __float2half(hv);
            Hs[h_l * HS_PITCH + b_l] = (uint32_t)*(uint16_t*)&hh;
        }
        __syncthreads();

        // ---- write h (and next x for jt==0) into next X buffer ----
        if (tid < 128) {
            const int b = b_base + tid;
            __half* Xo = &g_X[(t + 1) & 1][(size_t)b * KR];
            #pragma unroll
            for (int i = 0; i < 4; i++) {
                uint4 vh;
                uint32_t* ph = (uint32_t*)&vh;
                #pragma unroll
                for (int q = 0; q < 4; q++) {
                    uint32_t p0 = Hs[(i * 8 + q * 2) * HS_PITCH + tid];
                    uint32_t p1 = Hs[(i * 8 + q * 2 + 1) * HS_PITCH + tid];
                    ph[q] = p0 | (p1 << 16);
                }
                *(uint4*)(Xo + h0 + i * 8) = vh;
            }
            if (jt == 0 && t < TT - 1) {
                const __half* xs = g_xf16 + ((size_t)(t + 1) * BB + b) * DD;
                #pragma unroll
                for (int i = 0; i < 4; i++)
                    *(uint4*)(Xo + HH + i * 8) = *(const uint4*)(xs + i * 8);
            }
        }

        // ---- per-bm 8-CTA barrier ----
        if (t < TT - 1) {
            __syncthreads();
            if (tid == 0) {
                __threadfence();
                unsigned int v = atomicAdd(&g_cnt[bm * 32], 1);
                unsigned int target = (unsigned int)(t + 1);
                if (v == 7) {
                    g_cnt[bm * 32] = 0;
                    __threadfence();
                    g_phase[bm * 32] = target;
                } else {
                    while (g_phase[bm * 32] < target) {}
                    __threadfence();
                }
            }
            __syncthreads();
        }
    }
}

// ---------------- head ----------------
__global__ void head_kernel(const float* __restrict__ pm, float* __restrict__ out)
{
    int b = blockIdx.x * blockDim.x + threadIdx.x;
    if (b >= BB) return;
    const __half* Xrow = &g_X[0][(size_t)b * KR];   // T=128 even -> final h in buffer 0
    float s = g_beff;
    #pragma unroll 8
    for (int k = 0; k < HH; k++)
        s += __half2float(Xrow[k]) * g_weff[k];
    #pragma unroll
    for (int k = 0; k < PMM; k++) s += pm[b * PMM + k] * g_weff[HH + k];
    out[b] = s;
}

// ---------------- launch ----------------
extern "C" void kernel_launch(void* const* d_in, const int* in_sizes, int n_in,
                              void* d_out, int out_size)
{
    const float* x       = (const float*)d_in[0];
    const float* latlons = (const float*)d_in[1];
    const float* yearly  = (const float*)d_in[2];
    const float* pm      = (const float*)d_in[3];
    const float* Wf_i    = (const float*)d_in[4];
    const float* Wf_h    = (const float*)d_in[5];
    const float* bf      = (const float*)d_in[6];
    const float* Wu      = (const float*)d_in[7];
    const float* bu      = (const float*)d_in[8];
    const float* Wg_i    = (const float*)d_in[9];
    const float* Wg_h    = (const float*)d_in[10];
    const float* bg      = (const float*)d_in[11];
    const float* Wo_i    = (const float*)d_in[12];
    const float* Wo_h    = (const float*)d_in[13];
    const float* bo      = (const float*)d_in[14];
    const float* Wd0     = (const float*)d_in[15];
    const float* bd0     = (const float*)d_in[16];
    const float* Wd1     = (const float*)d_in[17];
    const float* bd1     = (const float*)d_in[18];

    static bool attr_set = false;
    if (!attr_set) {
        cudaFuncSetAttribute(step_persist, cudaFuncAttributeMaxDynamicSharedMemorySize, SMEM_TOTAL);
        attr_set = true;
    }

    prep_W<<<(KR * NTOT + 255) / 256, 256>>>(Wf_i, Wf_h, Wg_i, Wg_h, Wo_i, Wo_h);
    prep_bias<<<3, 256>>>(bf, bg, bo);
    prep_xf16<<<(int)(((size_t)TT * BB * DD + 255) / 256), 256>>>(x);
    prep_X0<<<(int)(((size_t)BB * KR + 255) / 256), 256>>>(x);
    prep_igate<<<(HH * BB + 255) / 256, 256>>>(latlons, yearly, Wu, bu);
    prep_head<<<1, 512>>>(Wd0, bd0, Wd1, bd1);

    step_persist<<<dim3(16, 8), 256, SMEM_TOTAL>>>();

    head_kernel<<<(BB + 255) / 256, 256>>>(pm, (float*)d_out);
}

// round 8
// speedup vs baseline: 4.1995x; 1.2130x over previous
#include <cuda_runtime.h>
#include <cuda_fp16.h>
#include <math.h>
#include <stdint.h>

#define BB 2048
#define TT 128
#define DD 32
#define HH 256
#define SS 39
#define PMM 12
#define KR 288              /* k layout: [h 256 | x 32] */
#define NTOT 768            /* j = gate*256 + h (gate-blocked) */
#define NCHUNK 3
#define NK16 18             /* 288/16 */

/* smem layout (bytes) */
#define A_PITCH 208                       /* 104 halfs: 96 data + 8 pad, odd x 16B */
#define A_STAGE (128 * A_PITCH)           /* 26624 */
#define W_ORIGIN (3 * A_STAGE)            /* 79872 */
#define W_PITCH 208
#define SMEM_TOTAL (W_ORIGIN + KR * W_PITCH)   /* 139776 */

// ---------------- device scratch ----------------
__device__ __half g_X[2][BB * KR];               // activations [b][k], ping-pong
__device__ __half g_W[KR * NTOT];                // weights [k][j], j = gate*256+h
__device__ __half g_xf16[(size_t)TT * BB * DD];  // per-t x fp16: [t][b][32]
__device__ float g_bias[NTOT];                   // [gate*256+h]
__device__ float g_ig[HH * BB];                  // input gate [h][b]
__device__ float g_weff[HH + PMM];
__device__ float g_beff;
__device__ unsigned int g_cnt[16 * 32];                 // per-bm barrier counters (128B apart)
__device__ volatile unsigned int g_phase[16 * 32];      // per-bm barrier phase

// ---------------- asm helpers ----------------
__device__ __forceinline__ uint32_t smem_u32(const void* p) {
    uint32_t a;
    asm("{ .reg .u64 t; cvta.to.shared.u64 t, %1; cvt.u32.u64 %0, t; }" : "=r"(a) : "l"(p));
    return a;
}
__device__ __forceinline__ void cp16(uint32_t dst, const void* src) {
    asm volatile("cp.async.cg.shared.global [%0], [%1], 16;" :: "r"(dst), "l"(src) : "memory");
}
__device__ __forceinline__ void cp_commit() {
    asm volatile("cp.async.commit_group;" ::: "memory");
}
template <int N>
__device__ __forceinline__ void cp_wait() {
    asm volatile("cp.async.wait_group %0;" :: "n"(N) : "memory");
}
__device__ __forceinline__ void ldm_x4(uint32_t* r, uint32_t addr) {
    asm volatile("ldmatrix.sync.aligned.m8n8.x4.shared.b16 {%0,%1,%2,%3}, [%4];"
                 : "=r"(r[0]), "=r"(r[1]), "=r"(r[2]), "=r"(r[3]) : "r"(addr));
}
__device__ __forceinline__ void ldm_x2t(uint32_t* r, uint32_t addr) {
    asm volatile("ldmatrix.sync.aligned.m8n8.x2.trans.shared.b16 {%0,%1}, [%2];"
                 : "=r"(r[0]), "=r"(r[1]) : "r"(addr));
}
__device__ __forceinline__ void mma16816(float* d, const uint32_t* a, const uint32_t* b) {
    asm volatile(
        "mma.sync.aligned.m16n8k16.row.col.f32.f16.f16.f32 "
        "{%0,%1,%2,%3}, {%4,%5,%6,%7}, {%8,%9}, {%0,%1,%2,%3};"
        : "+f"(d[0]), "+f"(d[1]), "+f"(d[2]), "+f"(d[3])
        : "r"(a[0]), "r"(a[1]), "r"(a[2]), "r"(a[3]), "r"(b[0]), "r"(b[1]));
}
__device__ __forceinline__ float tanh_fast(float x) {
    float y;
    asm("tanh.approx.f32 %0, %1;" : "=f"(y) : "f"(x));
    return y;
}
__device__ __forceinline__ float sigmoid_fast(float x) {
    return fmaf(0.5f, tanh_fast(0.5f * x), 0.5f);
}

// ---------------- prep kernels ----------------
__global__ void prep_W(const float* __restrict__ Wf_i, const float* __restrict__ Wf_h,
                       const float* __restrict__ Wg_i, const float* __restrict__ Wg_h,
                       const float* __restrict__ Wo_i, const float* __restrict__ Wo_h)
{
    int idx = blockIdx.x * blockDim.x + threadIdx.x;
    if (idx >= KR * NTOT) return;
    int k = idx / NTOT;
    int j = idx - k * NTOT;
    int gate = j >> 8, h = j & 255;
    const float* Wi = (gate == 0) ? Wf_i : (gate == 1) ? Wg_i : Wo_i;
    const float* Wh = (gate == 0) ? Wf_h : (gate == 1) ? Wg_h : Wo_h;
    float w = (k < HH) ? Wh[h * HH + k] : Wi[h * DD + (k - HH)];
    g_W[idx] = __float2half(w);
}

__global__ void prep_bias(const float* __restrict__ bf, const float* __restrict__ bg, const float* __restrict__ bo)
{
    int idx = blockIdx.x * blockDim.x + threadIdx.x;
    if (idx >= NTOT) return;
    int gate = idx >> 8, h = idx & 255;
    const float* b = (gate == 0) ? bf : (gate == 1) ? bg : bo;
    g_bias[idx] = b[h];
}

__global__ void prep_xf16(const float* __restrict__ x)
{
    size_t idx = (size_t)blockIdx.x * blockDim.x + threadIdx.x;
    if (idx >= (size_t)TT * BB * DD) return;
    int k = idx % DD;
    size_t tb = idx / DD;
    int b = tb % BB;
    int t = tb / BB;
    g_xf16[((size_t)t * BB + b) * DD + k] =
        __float2half(x[(size_t)b * (TT * DD) + (size_t)t * DD + k]);
}

__global__ void prep_X0(const float* __restrict__ x)
{
    size_t idx = (size_t)blockIdx.x * blockDim.x + threadIdx.x;
    if (idx >= (size_t)BB * KR) return;
    int k = idx % KR;
    int b = idx / KR;
    g_X[1][idx] = __float2half(0.0f);
    g_X[0][idx] = (k >= HH) ? __float2half(x[(size_t)b * (TT * DD) + (k - HH)]) : __float2half(0.0f);
}

__global__ void prep_igate(const float* __restrict__ latlons, const float* __restrict__ yearly,
                           const float* __restrict__ Wu, const float* __restrict__ bu)
{
    int idx = blockIdx.x * blockDim.x + threadIdx.x;
    if (idx >= HH * BB) return;
    int b = idx & (BB - 1);
    int h = idx >> 11;
    const float* w = Wu + h * SS;
    float s = bu[h];
    s += w[0] * latlons[b * 2 + 0];
    s += w[1] * latlons[b * 2 + 1];
    #pragma unroll
    for (int i = 0; i < 37; i++) s += w[2 + i] * yearly[b * 37 + i];
    g_ig[idx] = 1.0f / (1.0f + expf(-s));
}

__global__ void prep_head(const float* __restrict__ Wd0, const float* __restrict__ bd0,
                          const float* __restrict__ Wd1, const float* __restrict__ bd1)
{
    int idx = threadIdx.x;
    if (idx < HH + PMM) {
        float s = 0.0f;
        for (int m = 0; m < 256; m++) s += Wd1[m] * Wd0[m * (HH + PMM) + idx];
        g_weff[idx] = s;
    }
    if (idx == HH + PMM) {
        float s = bd1[0];
        for (int m = 0; m < 256; m++) s += Wd1[m] * bd0[m];
        g_beff = s;
    }
    if (idx >= 384 && idx < 400) {
        g_cnt[(idx - 384) * 32] = 0;
        g_phase[(idx - 384) * 32] = 0;
    }
}

// ---------------- persistent recurrent kernel ----------------
// 128 CTAs (16 bm x 8 jt), 1 CTA/SM. Warp nt = gate; epilogue fully register-local.
__global__ void __launch_bounds__(256, 1) step_persist()
{
    extern __shared__ char smem[];
    const uint32_t sb = smem_u32(smem);
    const int tid = threadIdx.x;
    const int wid = tid >> 5;
    const int lane = tid & 31;
    const int wm = wid & 1;        // 0..1 (64 batch rows)
    const int wn = wid >> 1;       // 0..3 (8 h cols)
    const int bm = blockIdx.x;     // 0..15
    const int jt = blockIdx.y;     // 0..7
    const int b_base = bm * 128;
    const int h0 = jt * 32;

    // thread's fixed (b,h) ownership
    const int r_base = b_base + wm * 64 + (lane >> 2);    // + mt*16 + rr*8
    const int hcol = h0 + wn * 8 + (lane & 3) * 2;        // 2 consecutive h

    // ---- prologue: W tile -> SMEM (once). cols = [gate0 32h | gate1 32h | gate2 32h] ----
    #pragma unroll
    for (int i = 0; i < 14; i++) {
        int slot = tid + i * 256;
        if (slot < KR * 12) {
            int row = slot / 12;
            int cq = slot - row * 12;
            int gate = cq >> 2;
            int within = cq & 3;
            cp16(sb + W_ORIGIN + row * W_PITCH + cq * 16,
                 g_W + (size_t)row * NTOT + gate * 256 + h0 + within * 8);
        }
    }
    cp_commit();

    // ---- prologue: ig + bias into registers, c = 0 ----
    float c_r[4][2][2];
    float ig_r[4][2][2];
    #pragma unroll
    for (int mt = 0; mt < 4; mt++)
        #pragma unroll
        for (int rr = 0; rr < 2; rr++)
            #pragma unroll
            for (int cc = 0; cc < 2; cc++) {
                c_r[mt][rr][cc] = 0.0f;
                ig_r[mt][rr][cc] = g_ig[(size_t)(hcol + cc) * BB + r_base + mt * 16 + rr * 8];
            }
    float bF[2], bG[2], bO[2];
    #pragma unroll
    for (int cc = 0; cc < 2; cc++) {
        bF[cc] = g_bias[0 * 256 + hcol + cc];
        bG[cc] = g_bias[1 * 256 + hcol + cc];
        bO[cc] = g_bias[2 * 256 + hcol + cc];
    }
    cp_wait<0>();
    __syncthreads();

    // ---- hoist W fragments into registers (gate = nt) ----
    uint32_t bfrag[NK16][3][2];
    {
        const uint32_t wb = sb + W_ORIGIN + (lane & 15) * W_PITCH + wn * 16;
        #pragma unroll
        for (int k16 = 0; k16 < NK16; k16++)
            #pragma unroll
            for (int gate = 0; gate < 3; gate++)
                ldm_x2t(bfrag[k16][gate], wb + k16 * (16 * W_PITCH) + gate * 64);
    }

    const uint32_t a_off = (uint32_t)((wm * 64 + (lane & 15)) * A_PITCH + (lane >> 4) * 16);

    for (int t = 0; t < TT; t++) {
        const __half* __restrict__ Xb = g_X[t & 1];

        // ---- issue all 3 A chunks (cp.async.cg: L2-only) ----
        #pragma unroll
        for (int c = 0; c < NCHUNK; c++) {
            #pragma unroll
            for (int i = 0; i < 6; i++) {
                int slot = tid + i * 256;
                int row = slot / 12;
                int cq = slot - row * 12;
                cp16(sb + c * A_STAGE + row * A_PITCH + cq * 16,
                     Xb + (size_t)(b_base + row) * KR + c * 96 + cq * 8);
            }
            cp_commit();
        }

        float acc[4][3][4];
        #pragma unroll
        for (int mt = 0; mt < 4; mt++)
            #pragma unroll
            for (int g = 0; g < 3; g++)
                #pragma unroll
                for (int q = 0; q < 4; q++) acc[mt][g][q] = 0.0f;

        // ---- MMA over 3 chunks x 6 k16 ----
        #pragma unroll
        for (int c = 0; c < NCHUNK; c++) {
            if (c == 0) cp_wait<2>();
            else if (c == 1) cp_wait<1>();
            else cp_wait<0>();
            __syncthreads();
            const uint32_t aB = sb + c * A_STAGE + a_off;
            #pragma unroll
            for (int kk = 0; kk < 6; kk++) {
                uint32_t af[4][4];
                #pragma unroll
                for (int mt = 0; mt < 4; mt++)
                    ldm_x4(af[mt], aB + mt * (16 * A_PITCH) + kk * 32);
                #pragma unroll
                for (int mt = 0; mt < 4; mt++)
                    #pragma unroll
                    for (int g = 0; g < 3; g++)
                        mma16816(acc[mt][g], af[mt], bfrag[c * 6 + kk][g]);
            }
        }

        // ---- register-local epilogue: gates, state update, direct STG ----
        __half* Xo = &g_X[(t + 1) & 1][0];
        #pragma unroll
        for (int mt = 0; mt < 4; mt++)
            #pragma unroll
            for (int rr = 0; rr < 2; rr++) {
                uint32_t pk;
                __half2* hp = (__half2*)&pk;
                #pragma unroll
                for (int cc = 0; cc < 2; cc++) {
                    float fp = acc[mt][0][rr * 2 + cc] + bF[cc];
                    float gp = acc[mt][1][rr * 2 + cc] + bG[cc];
                    float op = acc[mt][2][rr * 2 + cc] + bO[cc];
                    float f = sigmoid_fast(fp);
                    float g = tanh_fast(gp);
                    float o = sigmoid_fast(op);
                    float c1 = f * c_r[mt][rr][cc] + ig_r[mt][rr][cc] * g;
                    c_r[mt][rr][cc] = c1;
                    float hv = o * tanh_fast(c1);
                    ((__half*)hp)[cc] = __float2half(hv);
                }
                int b = r_base + mt * 16 + rr * 8;
                *(uint32_t*)(Xo + (size_t)b * KR + hcol) = pk;
            }

        // ---- next x slice (jt==0 CTAs) ----
        if (jt == 0 && t < TT - 1 && tid < 128) {
            const int b = b_base + tid;
            const __half* xs = g_xf16 + ((size_t)(t + 1) * BB + b) * DD;
            #pragma unroll
            for (int i = 0; i < 4; i++)
                *(uint4*)(Xo + (size_t)b * KR + HH + i * 8) = *(const uint4*)(xs + i * 8);
        }

        // ---- per-bm 8-CTA barrier ----
        if (t < TT - 1) {
            __syncthreads();
            if (tid == 0) {
                __threadfence();
                unsigned int v = atomicAdd(&g_cnt[bm * 32], 1);
                unsigned int target = (unsigned int)(t + 1);
                if (v == 7) {
                    g_cnt[bm * 32] = 0;
                    __threadfence();
                    g_phase[bm * 32] = target;
                } else {
                    while (g_phase[bm * 32] < target) {}
                    __threadfence();
                }
            }
            __syncthreads();
        }
    }
}

// ---------------- head ----------------
__global__ void head_kernel(const float* __restrict__ pm, float* __restrict__ out)
{
    int b = blockIdx.x * blockDim.x + threadIdx.x;
    if (b >= BB) return;
    const __half* Xrow = &g_X[0][(size_t)b * KR];   // T=128 even -> final h in buffer 0
    float s = g_beff;
    #pragma unroll 8
    for (int k = 0; k < HH; k++)
        s += __half2float(Xrow[k]) * g_weff[k];
    #pragma unroll
    for (int k = 0; k < PMM; k++) s += pm[b * PMM + k] * g_weff[HH + k];
    out[b] = s;
}

// ---------------- launch ----------------
extern "C" void kernel_launch(void* const* d_in, const int* in_sizes, int n_in,
                              void* d_out, int out_size)
{
    const float* x       = (const float*)d_in[0];
    const float* latlons = (const float*)d_in[1];
    const float* yearly  = (const float*)d_in[2];
    const float* pm      = (const float*)d_in[3];
    const float* Wf_i    = (const float*)d_in[4];
    const float* Wf_h    = (const float*)d_in[5];
    const float* bf      = (const float*)d_in[6];
    const float* Wu      = (const float*)d_in[7];
    const float* bu      = (const float*)d_in[8];
    const float* Wg_i    = (const float*)d_in[9];
    const float* Wg_h    = (const float*)d_in[10];
    const float* bg      = (const float*)d_in[11];
    const float* Wo_i    = (const float*)d_in[12];
    const float* Wo_h    = (const float*)d_in[13];
    const float* bo      = (const float*)d_in[14];
    const float* Wd0     = (const float*)d_in[15];
    const float* bd0     = (const float*)d_in[16];
    const float* Wd1     = (const float*)d_in[17];
    const float* bd1     = (const float*)d_in[18];

    static bool attr_set = false;
    if (!attr_set) {
        cudaFuncSetAttribute(step_persist, cudaFuncAttributeMaxDynamicSharedMemorySize, SMEM_TOTAL);
        attr_set = true;
    }

    prep_W<<<(KR * NTOT + 255) / 256, 256>>>(Wf_i, Wf_h, Wg_i, Wg_h, Wo_i, Wo_h);
    prep_bias<<<3, 256>>>(bf, bg, bo);
    prep_xf16<<<(int)(((size_t)TT * BB * DD + 255) / 256), 256>>>(x);
    prep_X0<<<(int)(((size_t)BB * KR + 255) / 256), 256>>>(x);
    prep_igate<<<(HH * BB + 255) / 256, 256>>>(latlons, yearly, Wu, bu);
    prep_head<<<1, 512>>>(Wd0, bd0, Wd1, bd1);

    step_persist<<<dim3(16, 8), 256, SMEM_TOTAL>>>();

    head_kernel<<<(BB + 255) / 256, 256>>>(pm, (float*)d_out);
}

// round 9
// speedup vs baseline: 4.7956x; 1.1419x over previous
#include <cuda_runtime.h>
#include <cuda_fp16.h>
#include <math.h>
#include <stdint.h>

#define BB 2048
#define TT 128
#define DD 32
#define HH 256
#define SS 39
#define PMM 12
#define KR 288              /* k layout: [h 256 | x 32] */
#define NTOT 768            /* j = gate*256 + h (gate-blocked) */
#define NCHUNK 2
#define KB 144
#define NK16 18             /* 288/16 */

/* smem layout (bytes) */
#define A_PITCH 304                       /* 152 halfs: 144 data + 8 pad, odd x 16B */
#define A_STAGE (128 * A_PITCH)           /* 38912 */
#define W_ORIGIN (2 * A_STAGE)            /* 77824 */
#define W_PITCH 208                       /* 104 halfs: 96 data + 8 pad */
#define SMEM_TOTAL (W_ORIGIN + KR * W_PITCH)   /* 137728 */

// ---------------- device scratch ----------------
__device__ __half g_X[2][BB * KR];               // activations [b][k], ping-pong
__device__ __half g_W[KR * NTOT];                // weights [k][j], j = gate*256+h
__device__ float g_bias[NTOT];                   // [gate*256+h]
__device__ float g_ig[HH * BB];                  // input gate [h][b]
__device__ float g_weff[HH + PMM];
__device__ float g_beff;
__device__ unsigned int g_cnt[16 * 32];          // per-bm monotone arrival counters (128B apart)

// ---------------- asm helpers ----------------
__device__ __forceinline__ uint32_t smem_u32(const void* p) {
    uint32_t a;
    asm("{ .reg .u64 t; cvta.to.shared.u64 t, %1; cvt.u32.u64 %0, t; }" : "=r"(a) : "l"(p));
    return a;
}
__device__ __forceinline__ void cp16(uint32_t dst, const void* src) {
    asm volatile("cp.async.cg.shared.global [%0], [%1], 16;" :: "r"(dst), "l"(src) : "memory");
}
__device__ __forceinline__ void cp_commit() {
    asm volatile("cp.async.commit_group;" ::: "memory");
}
template <int N>
__device__ __forceinline__ void cp_wait() {
    asm volatile("cp.async.wait_group %0;" :: "n"(N) : "memory");
}
__device__ __forceinline__ void ldm_x4(uint32_t* r, uint32_t addr) {
    asm volatile("ldmatrix.sync.aligned.m8n8.x4.shared.b16 {%0,%1,%2,%3}, [%4];"
                 : "=r"(r[0]), "=r"(r[1]), "=r"(r[2]), "=r"(r[3]) : "r"(addr));
}
__device__ __forceinline__ void ldm_x2t(uint32_t* r, uint32_t addr) {
    asm volatile("ldmatrix.sync.aligned.m8n8.x2.trans.shared.b16 {%0,%1}, [%2];"
                 : "=r"(r[0]), "=r"(r[1]) : "r"(addr));
}
__device__ __forceinline__ void mma16816(float* d, const uint32_t* a, const uint32_t* b) {
    asm volatile(
        "mma.sync.aligned.m16n8k16.row.col.f32.f16.f16.f32 "
        "{%0,%1,%2,%3}, {%4,%5,%6,%7}, {%8,%9}, {%0,%1,%2,%3};"
        : "+f"(d[0]), "+f"(d[1]), "+f"(d[2]), "+f"(d[3])
        : "r"(a[0]), "r"(a[1]), "r"(a[2]), "r"(a[3]), "r"(b[0]), "r"(b[1]));
}
__device__ __forceinline__ float tanh_fast(float x) {
    float y;
    asm("tanh.approx.f32 %0, %1;" : "=f"(y) : "f"(x));
    return y;
}
__device__ __forceinline__ float sigmoid_fast(float x) {
    return fmaf(0.5f, tanh_fast(0.5f * x), 0.5f);
}
__device__ __forceinline__ void red_release(unsigned int* p) {
    asm volatile("red.release.gpu.global.add.u32 [%0], 1;" :: "l"(p) : "memory");
}
__device__ __forceinline__ unsigned int ld_acquire(const unsigned int* p) {
    unsigned int v;
    asm volatile("ld.acquire.gpu.global.u32 %0, [%1];" : "=r"(v) : "l"(p) : "memory");
    return v;
}

// ---------------- fused prep (one launch) ----------------
// blocks [0,864): W pack | 864: bias | [865,1153): X[0] init | [1153,3201): igate | 3201: head+flags
__global__ void prep_all(const float* __restrict__ x,
                         const float* __restrict__ latlons, const float* __restrict__ yearly,
                         const float* __restrict__ Wu, const float* __restrict__ bu,
                         const float* __restrict__ Wf_i, const float* __restrict__ Wf_h, const float* __restrict__ bf,
                         const float* __restrict__ Wg_i, const float* __restrict__ Wg_h, const float* __restrict__ bg,
                         const float* __restrict__ Wo_i, const float* __restrict__ Wo_h, const float* __restrict__ bo,
                         const float* __restrict__ Wd0, const float* __restrict__ bd0,
                         const float* __restrict__ Wd1, const float* __restrict__ bd1)
{
    const int blk = blockIdx.x;
    const int tid = threadIdx.x;
    if (blk < 864) {                       // ---- W pack: KR*NTOT = 221184 elems ----
        int idx = blk * 256 + tid;
        if (idx < KR * NTOT) {
            int k = idx / NTOT;
            int j = idx - k * NTOT;
            int gate = j >> 8, h = j & 255;
            const float* Wi = (gate == 0) ? Wf_i : (gate == 1) ? Wg_i : Wo_i;
            const float* Wh = (gate == 0) ? Wf_h : (gate == 1) ? Wg_h : Wo_h;
            float w = (k < HH) ? Wh[h * HH + k] : Wi[h * DD + (k - HH)];
            g_W[idx] = __float2half(w);
        }
    } else if (blk == 864) {               // ---- bias ----
        for (int idx = tid; idx < NTOT; idx += 256) {
            int gate = idx >> 8, h = idx & 255;
            const float* b = (gate == 0) ? bf : (gate == 1) ? bg : bo;
            g_bias[idx] = b[h];
        }
    } else if (blk < 1153) {               // ---- X[0]: zeros + x[:,0,:] (16B per thread) ----
        int gid = (blk - 865) * 256 + tid;       // < 73728
        int idx8 = gid * 8;
        int b = idx8 / KR;
        int k0 = idx8 - b * KR;
        uint4 out = make_uint4(0, 0, 0, 0);
        if (k0 >= HH) {
            const float* xr = x + (size_t)b * (TT * DD) + (k0 - HH);
            float4 v0 = *(const float4*)xr;
            float4 v1 = *(const float4*)(xr + 4);
            __half2 h0 = __floats2half2_rn(v0.x, v0.y);
            __half2 h1 = __floats2half2_rn(v0.z, v0.w);
            __half2 h2 = __floats2half2_rn(v1.x, v1.y);
            __half2 h3 = __floats2half2_rn(v1.z, v1.w);
            out = make_uint4(*(uint32_t*)&h0, *(uint32_t*)&h1, *(uint32_t*)&h2, *(uint32_t*)&h3);
        }
        *(uint4*)&g_X[0][(size_t)b * KR + k0] = out;
    } else if (blk < 3201) {               // ---- igate ----
        int idx = (blk - 1153) * 256 + tid;      // < HH*BB
        int b = idx & (BB - 1);
        int h = idx >> 11;
        const float* w = Wu + h * SS;
        float s = bu[h];
        s += w[0] * latlons[b * 2 + 0];
        s += w[1] * latlons[b * 2 + 1];
        #pragma unroll
        for (int i = 0; i < 37; i++) s += w[2 + i] * yearly[b * 37 + i];
        g_ig[idx] = 1.0f / (1.0f + expf(-s));
    } else {                               // ---- head collapse + barrier flags ----
        for (int idx = tid; idx < HH + PMM; idx += 256) {
            float s = 0.0f;
            for (int m = 0; m < 256; m++) s += Wd1[m] * Wd0[m * (HH + PMM) + idx];
            g_weff[idx] = s;
        }
        if (tid == 0) {
            float s = bd1[0];
            for (int m = 0; m < 256; m++) s += Wd1[m] * bd0[m];
            g_beff = s;
        }
        if (tid < 16) g_cnt[tid * 32] = 0;
    }
}

// ---------------- persistent recurrent kernel ----------------
// 128 CTAs (16 bm x 8 jt), 1 CTA/SM. Register-local epilogue; on-the-fly x convert.
__global__ void __launch_bounds__(256, 1) step_persist(const float* __restrict__ xg)
{
    extern __shared__ char smem[];
    const uint32_t sb = smem_u32(smem);
    const int tid = threadIdx.x;
    const int lane = tid & 31;
    const int wm = (tid >> 5) & 1;    // 0..1 (64 batch rows)
    const int wn = tid >> 6;          // 0..3 (8 h cols)
    const int bm = blockIdx.x;        // 0..15
    const int jt = blockIdx.y;        // 0..7
    const int b_base = bm * 128;
    const int h0 = jt * 32;

    // thread's fixed (b,h) ownership
    const int r_base = b_base + wm * 64 + (lane >> 2);    // + mt*16 + rr*8
    const int hcol = h0 + wn * 8 + (lane & 3) * 2;        // 2 consecutive h

    // ---- prologue: W tile -> SMEM (once). cols = [gate0 32h | gate1 32h | gate2 32h] ----
    #pragma unroll
    for (int i = 0; i < 14; i++) {
        int slot = tid + i * 256;
        if (slot < KR * 12) {
            int row = slot / 12;
            int cq = slot - row * 12;
            int gate = cq >> 2;
            int within = cq & 3;
            cp16(sb + W_ORIGIN + row * W_PITCH + cq * 16,
                 g_W + (size_t)row * NTOT + gate * 256 + h0 + within * 8);
        }
    }
    cp_commit();

    // ---- prologue: ig + bias into registers, c = 0 ----
    float c_r[4][2][2];
    float ig_r[4][2][2];
    #pragma unroll
    for (int mt = 0; mt < 4; mt++)
        #pragma unroll
        for (int rr = 0; rr < 2; rr++)
            #pragma unroll
            for (int cc = 0; cc < 2; cc++) {
                c_r[mt][rr][cc] = 0.0f;
                ig_r[mt][rr][cc] = g_ig[(size_t)(hcol + cc) * BB + r_base + mt * 16 + rr * 8];
            }
    float bF[2], bG[2], bO[2];
    #pragma unroll
    for (int cc = 0; cc < 2; cc++) {
        bF[cc] = g_bias[0 * 256 + hcol + cc];
        bG[cc] = g_bias[1 * 256 + hcol + cc];
        bO[cc] = g_bias[2 * 256 + hcol + cc];
    }
    cp_wait<0>();
    __syncthreads();

    // ---- hoist W fragments into registers (gate = nt) ----
    uint32_t bfrag[NK16][3][2];
    {
        const uint32_t wb = sb + W_ORIGIN + (lane & 15) * W_PITCH + wn * 16;
        #pragma unroll
        for (int k16 = 0; k16 < NK16; k16++)
            #pragma unroll
            for (int gate = 0; gate < 3; gate++)
                ldm_x2t(bfrag[k16][gate], wb + k16 * (16 * W_PITCH) + gate * 64);
    }

    const uint32_t a_off = (uint32_t)((wm * 64 + (lane & 15)) * A_PITCH + (lane >> 4) * 16);

    for (int t = 0; t < TT; t++) {
        const __half* __restrict__ Xb = g_X[t & 1];
        __half* Xo = &g_X[(t + 1) & 1][0];

        // ---- on-the-fly x convert for t+1 (independent of barrier; latency hidden) ----
        if (jt == 0 && t < TT - 1 && tid < 128) {
            const int b = b_base + tid;
            const float* xr = xg + (size_t)b * (TT * DD) + (size_t)(t + 1) * DD;
            __half* dst = Xo + (size_t)b * KR + HH;
            #pragma unroll
            for (int i = 0; i < 4; i++) {
                float4 v0 = *(const float4*)(xr + i * 8);
                float4 v1 = *(const float4*)(xr + i * 8 + 4);
                __half2 p0 = __floats2half2_rn(v0.x, v0.y);
                __half2 p1 = __floats2half2_rn(v0.z, v0.w);
                __half2 p2 = __floats2half2_rn(v1.x, v1.y);
                __half2 p3 = __floats2half2_rn(v1.z, v1.w);
                uint4 pk = make_uint4(*(uint32_t*)&p0, *(uint32_t*)&p1,
                                      *(uint32_t*)&p2, *(uint32_t*)&p3);
                *(uint4*)(dst + i * 8) = pk;
            }
        }

        // ---- issue both A chunks (cp.async.cg: L2-only) ----
        #pragma unroll
        for (int c = 0; c < NCHUNK; c++) {
            #pragma unroll
            for (int i = 0; i < 9; i++) {
                int slot = tid + i * 256;
                int row = slot / 18;
                int cq = slot - row * 18;
                cp16(sb + c * A_STAGE + row * A_PITCH + cq * 16,
                     Xb + (size_t)(b_base + row) * KR + c * KB + cq * 8);
            }
            cp_commit();
        }

        float acc[4][3][4];
        #pragma unroll
        for (int mt = 0; mt < 4; mt++)
            #pragma unroll
            for (int g = 0; g < 3; g++)
                #pragma unroll
                for (int q = 0; q < 4; q++) acc[mt][g][q] = 0.0f;

        // ---- MMA over 2 chunks x 9 k16 ----
        #pragma unroll
        for (int c = 0; c < NCHUNK; c++) {
            if (c == 0) cp_wait<1>();
            else cp_wait<0>();
            __syncthreads();
            const uint32_t aB = sb + c * A_STAGE + a_off;
            #pragma unroll
            for (int kk = 0; kk < 9; kk++) {
                uint32_t af[4][4];
                #pragma unroll
                for (int mt = 0; mt < 4; mt++)
                    ldm_x4(af[mt], aB + mt * (16 * A_PITCH) + kk * 32);
                #pragma unroll
                for (int mt = 0; mt < 4; mt++)
                    #pragma unroll
                    for (int g = 0; g < 3; g++)
                        mma16816(acc[mt][g], af[mt], bfrag[c * 9 + kk][g]);
            }
        }

        // ---- register-local epilogue: gates, state update, direct STG ----
        #pragma unroll
        for (int mt = 0; mt < 4; mt++)
            #pragma unroll
            for (int rr = 0; rr < 2; rr++) {
                uint32_t pk;
                __half2* hp = (__half2*)&pk;
                #pragma unroll
                for (int cc = 0; cc < 2; cc++) {
                    float fp = acc[mt][0][rr * 2 + cc] + bF[cc];
                    float gp = acc[mt][1][rr * 2 + cc] + bG[cc];
                    float op = acc[mt][2][rr * 2 + cc] + bO[cc];
                    float f = sigmoid_fast(fp);
                    float g = tanh_fast(gp);
                    float o = sigmoid_fast(op);
                    float c1 = f * c_r[mt][rr][cc] + ig_r[mt][rr][cc] * g;
                    c_r[mt][rr][cc] = c1;
                    float hv = o * tanh_fast(c1);
                    ((__half*)hp)[cc] = __float2half(hv);
                }
                int b = r_base + mt * 16 + rr * 8;
                *(uint32_t*)(Xo + (size_t)b * KR + hcol) = pk;
            }

        // ---- per-bm release/acquire barrier (monotone counter) ----
        if (t < TT - 1) {
            __syncthreads();
            if (tid == 0) {
                red_release(&g_cnt[bm * 32]);
                const unsigned int target = 8u * (unsigned int)(t + 1);
                while (ld_acquire(&g_cnt[bm * 32]) < target) {}
            }
            __syncthreads();
        }
    }
}

// ---------------- head ----------------
__global__ void head_kernel(const float* __restrict__ pm, float* __restrict__ out)
{
    int b = blockIdx.x * blockDim.x + threadIdx.x;
    if (b >= BB) return;
    const __half* Xrow = &g_X[0][(size_t)b * KR];   // T=128 even -> final h in buffer 0
    float s = g_beff;
    #pragma unroll 8
    for (int k = 0; k < HH; k++)
        s += __half2float(Xrow[k]) * g_weff[k];
    #pragma unroll
    for (int k = 0; k < PMM; k++) s += pm[b * PMM + k] * g_weff[HH + k];
    out[b] = s;
}

// ---------------- launch ----------------
extern "C" void kernel_launch(void* const* d_in, const int* in_sizes, int n_in,
                              void* d_out, int out_size)
{
    const float* x       = (const float*)d_in[0];
    const float* latlons = (const float*)d_in[1];
    const float* yearly  = (const float*)d_in[2];
    const float* pm      = (const float*)d_in[3];
    const float* Wf_i    = (const float*)d_in[4];
    const float* Wf_h    = (const float*)d_in[5];
    const float* bf      = (const float*)d_in[6];
    const float* Wu      = (const float*)d_in[7];
    const float* bu      = (const float*)d_in[8];
    const float* Wg_i    = (const float*)d_in[9];
    const float* Wg_h    = (const float*)d_in[10];
    const float* bg      = (const float*)d_in[11];
    const float* Wo_i    = (const float*)d_in[12];
    const float* Wo_h    = (const float*)d_in[13];
    const float* bo      = (const float*)d_in[14];
    const float* Wd0     = (const float*)d_in[15];
    const float* bd0     = (const float*)d_in[16];
    const float* Wd1     = (const float*)d_in[17];
    const float* bd1     = (const float*)d_in[18];

    static bool attr_set = false;
    if (!attr_set) {
        cudaFuncSetAttribute(step_persist, cudaFuncAttributeMaxDynamicSharedMemorySize, SMEM_TOTAL);
        attr_set = true;
    }

    prep_all<<<3202, 256>>>(x, latlons, yearly, Wu, bu,
                            Wf_i, Wf_h, bf, Wg_i, Wg_h, bg, Wo_i, Wo_h, bo,
                            Wd0, bd0, Wd1, bd1);

    step_persist<<<dim3(16, 8), 256, SMEM_TOTAL>>>(x);

    head_kernel<<<(BB + 255) / 256, 256>>>(pm, (float*)d_out);
}

// round 10
// speedup vs baseline: 5.0668x; 1.0566x over previous
#include <cuda_runtime.h>
#include <cuda_fp16.h>
#include <math.h>
#include <stdint.h>

#define BB 2048
#define TT 128
#define DD 32
#define HH 256
#define SS 39
#define PMM 12
#define KR 288              /* k layout: [h 256 | x 32] */
#define NCHUNK 2
#define KB 144
#define NK16 18             /* 288/16 */

/* smem layout (bytes) */
#define A_PITCH 304                       /* 152 halfs: 144 data + 8 pad, odd x 16B */
#define A_STAGE (128 * A_PITCH)           /* 38912 */
#define W_ORIGIN (2 * A_STAGE)            /* 77824 */
#define W_PITCH 208                       /* 104 halfs: 96 data + 8 pad */
#define SMEM_TOTAL (W_ORIGIN + KR * W_PITCH)   /* 137728 */

// ---------------- device scratch ----------------
__device__ __half g_X[2][BB * KR];               // activations [b][k], ping-pong
__device__ float g_weff[HH + PMM];
__device__ float g_beff;
__device__ unsigned int g_cnt[16 * 32];          // per-bm monotone arrival counters (128B apart)

// ---------------- asm helpers ----------------
__device__ __forceinline__ uint32_t smem_u32(const void* p) {
    uint32_t a;
    asm("{ .reg .u64 t; cvta.to.shared.u64 t, %1; cvt.u32.u64 %0, t; }" : "=r"(a) : "l"(p));
    return a;
}
__device__ __forceinline__ void cp16(uint32_t dst, const void* src) {
    asm volatile("cp.async.cg.shared.global [%0], [%1], 16;" :: "r"(dst), "l"(src) : "memory");
}
__device__ __forceinline__ void cp_commit() {
    asm volatile("cp.async.commit_group;" ::: "memory");
}
template <int N>
__device__ __forceinline__ void cp_wait() {
    asm volatile("cp.async.wait_group %0;" :: "n"(N) : "memory");
}
__device__ __forceinline__ void ldm_x4(uint32_t* r, uint32_t addr) {
    asm volatile("ldmatrix.sync.aligned.m8n8.x4.shared.b16 {%0,%1,%2,%3}, [%4];"
                 : "=r"(r[0]), "=r"(r[1]), "=r"(r[2]), "=r"(r[3]) : "r"(addr));
}
__device__ __forceinline__ void ldm_x2t(uint32_t* r, uint32_t addr) {
    asm volatile("ldmatrix.sync.aligned.m8n8.x2.trans.shared.b16 {%0,%1}, [%2];"
                 : "=r"(r[0]), "=r"(r[1]) : "r"(addr));
}
__device__ __forceinline__ void mma16816(float* d, const uint32_t* a, const uint32_t* b) {
    asm volatile(
        "mma.sync.aligned.m16n8k16.row.col.f32.f16.f16.f32 "
        "{%0,%1,%2,%3}, {%4,%5,%6,%7}, {%8,%9}, {%0,%1,%2,%3};"
        : "+f"(d[0]), "+f"(d[1]), "+f"(d[2]), "+f"(d[3])
        : "r"(a[0]), "r"(a[1]), "r"(a[2]), "r"(a[3]), "r"(b[0]), "r"(b[1]));
}
__device__ __forceinline__ float tanh_fast(float x) {
    float y;
    asm("tanh.approx.f32 %0, %1;" : "=f"(y) : "f"(x));
    return y;
}
__device__ __forceinline__ float sigmoid_fast(float x) {
    return fmaf(0.5f, tanh_fast(0.5f * x), 0.5f);
}
__device__ __forceinline__ void red_release(unsigned int* p) {
    asm volatile("red.release.gpu.global.add.u32 [%0], 1;" :: "l"(p) : "memory");
}
__device__ __forceinline__ unsigned int ld_acquire(const unsigned int* p) {
    unsigned int v;
    asm volatile("ld.acquire.gpu.global.u32 %0, [%1];" : "=r"(v) : "l"(p) : "memory");
    return v;
}

// ---------------- slim prep (one launch, 289 blocks) ----------------
// blocks [0,288): X[0] init | 288: head collapse + counters
__global__ void prep_all(const float* __restrict__ x,
                         const float* __restrict__ Wd0, const float* __restrict__ bd0,
                         const float* __restrict__ Wd1, const float* __restrict__ bd1)
{
    const int blk = blockIdx.x;
    const int tid = threadIdx.x;
    if (blk < 288) {                       // ---- X[0]: zeros + x[:,0,:] (16B per thread) ----
        int gid = blk * 256 + tid;               // < 73728
        int idx8 = gid * 8;
        int b = idx8 / KR;
        int k0 = idx8 - b * KR;
        uint4 out = make_uint4(0, 0, 0, 0);
        if (k0 >= HH) {
            const float* xr = x + (size_t)b * (TT * DD) + (k0 - HH);
            float4 v0 = *(const float4*)xr;
            float4 v1 = *(const float4*)(xr + 4);
            __half2 h0 = __floats2half2_rn(v0.x, v0.y);
            __half2 h1 = __floats2half2_rn(v0.z, v0.w);
            __half2 h2 = __floats2half2_rn(v1.x, v1.y);
            __half2 h3 = __floats2half2_rn(v1.z, v1.w);
            out = make_uint4(*(uint32_t*)&h0, *(uint32_t*)&h1, *(uint32_t*)&h2, *(uint32_t*)&h3);
        }
        *(uint4*)&g_X[0][(size_t)b * KR + k0] = out;
    } else {                               // ---- head collapse + barrier counters ----
        for (int idx = tid; idx < HH + PMM; idx += 256) {
            float s = 0.0f;
            for (int m = 0; m < 256; m++) s += Wd1[m] * Wd0[m * (HH + PMM) + idx];
            g_weff[idx] = s;
        }
        if (tid == 0) {
            float s = bd1[0];
            for (int m = 0; m < 256; m++) s += Wd1[m] * bd0[m];
            g_beff = s;
        }
        if (tid < 16) g_cnt[tid * 32] = 0;
    }
}

// ---------------- persistent recurrent kernel ----------------
// 128 CTAs (16 bm x 8 jt), 1 CTA/SM. All one-time prep folded into prologue.
__global__ void __launch_bounds__(256, 1) step_persist(
    const float* __restrict__ xg,
    const float* __restrict__ latlons, const float* __restrict__ yearly,
    const float* __restrict__ Wu, const float* __restrict__ bu,
    const float* __restrict__ Wf_i, const float* __restrict__ Wf_h, const float* __restrict__ bf,
    const float* __restrict__ Wg_i, const float* __restrict__ Wg_h, const float* __restrict__ bg,
    const float* __restrict__ Wo_i, const float* __restrict__ Wo_h, const float* __restrict__ bo)
{
    extern __shared__ char smem[];
    const uint32_t sb = smem_u32(smem);
    const int tid = threadIdx.x;
    const int lane = tid & 31;
    const int wid = tid >> 5;
    const int wm = wid & 1;           // 0..1 (64 batch rows)
    const int wn = wid >> 1;          // 0..3 (8 h cols)
    const int bm = blockIdx.x;        // 0..15
    const int jt = blockIdx.y;        // 0..7
    const int b_base = bm * 128;
    const int h0 = jt * 32;

    // thread's fixed (b,h) ownership
    const int r_base = b_base + wm * 64 + (lane >> 2);    // + mt*16 + rr*8
    const int hcol = h0 + wn * 8 + (lane & 3) * 2;        // 2 consecutive h

    // ---- prologue: W tile gathered DIRECTLY from raw fp32 weights -> SMEM ----
    // cols: [gate0 h0..h0+31 | gate1 ... | gate2 ...]; warp wid owns 12 cols, lanes sweep k.
    {
        __half* Wrow = (__half*)(smem + W_ORIGIN);
        #pragma unroll
        for (int ci = 0; ci < 12; ci++) {
            int col = wid * 12 + ci;
            int gate = col >> 5;              // 0..2
            int hh = col & 31;
            const float* Whg = (gate == 0) ? Wf_h : (gate == 1) ? Wg_h : Wo_h;
            const float* Wig = (gate == 0) ? Wf_i : (gate == 1) ? Wg_i : Wo_i;
            const float* hrow = Whg + (size_t)(h0 + hh) * HH;
            const float* irow = Wig + (size_t)(h0 + hh) * DD;
            #pragma unroll
            for (int it = 0; it < 9; it++) {
                int k = it * 32 + lane;
                float v = (k < HH) ? hrow[k] : irow[k - HH];
                Wrow[k * 104 + col] = __float2half(v);
            }
        }
    }

    // ---- prologue: bias direct LDG ----
    float bF[2], bG[2], bO[2];
    #pragma unroll
    for (int cc = 0; cc < 2; cc++) {
        bF[cc] = bf[hcol + cc];
        bG[cc] = bg[hcol + cc];
        bO[cc] = bo[hcol + cc];
    }

    // ---- prologue: i_gate computed in-place into registers, c = 0 ----
    float c_r[4][2][2];
    float ig_r[4][2][2];
    #pragma unroll
    for (int mt = 0; mt < 4; mt++)
        #pragma unroll
        for (int rr = 0; rr < 2; rr++) {
            const int b = r_base + mt * 16 + rr * 8;
            const float ll0 = latlons[b * 2 + 0];
            const float ll1 = latlons[b * 2 + 1];
            const float* yr = yearly + (size_t)b * 37;
            #pragma unroll
            for (int cc = 0; cc < 2; cc++) {
                const int h = hcol + cc;
                const float* w = Wu + h * SS;
                float s = bu[h] + w[0] * ll0 + w[1] * ll1;
                #pragma unroll
                for (int i = 0; i < 37; i++) s += w[2 + i] * yr[i];
                ig_r[mt][rr][cc] = sigmoid_fast(s);
                c_r[mt][rr][cc] = 0.0f;
            }
        }
    __syncthreads();

    // ---- hoist W fragments into registers (gate = nt) ----
    uint32_t bfrag[NK16][3][2];
    {
        const uint32_t wb = sb + W_ORIGIN + (lane & 15) * W_PITCH + wn * 16;
        #pragma unroll
        for (int k16 = 0; k16 < NK16; k16++)
            #pragma unroll
            for (int gate = 0; gate < 3; gate++)
                ldm_x2t(bfrag[k16][gate], wb + k16 * (16 * W_PITCH) + gate * 64);
    }

    const uint32_t a_off = (uint32_t)((wm * 64 + (lane & 15)) * A_PITCH + (lane >> 4) * 16);

    for (int t = 0; t < TT; t++) {
        const __half* __restrict__ Xb = g_X[t & 1];
        __half* Xo = &g_X[(t + 1) & 1][0];

        // ---- on-the-fly x convert for t+1 (latency hidden behind MMA phase) ----
        if (jt == 0 && t < TT - 1 && tid < 128) {
            const int b = b_base + tid;
            const float* xr = xg + (size_t)b * (TT * DD) + (size_t)(t + 1) * DD;
            __half* dst = Xo + (size_t)b * KR + HH;
            #pragma unroll
            for (int i = 0; i < 4; i++) {
                float4 v0 = *(const float4*)(xr + i * 8);
                float4 v1 = *(const float4*)(xr + i * 8 + 4);
                __half2 p0 = __floats2half2_rn(v0.x, v0.y);
                __half2 p1 = __floats2half2_rn(v0.z, v0.w);
                __half2 p2 = __floats2half2_rn(v1.x, v1.y);
                __half2 p3 = __floats2half2_rn(v1.z, v1.w);
                uint4 pk = make_uint4(*(uint32_t*)&p0, *(uint32_t*)&p1,
                                      *(uint32_t*)&p2, *(uint32_t*)&p3);
                *(uint4*)(dst + i * 8) = pk;
            }
        }

        // ---- issue both A chunks (cp.async.cg: L2-only) ----
        #pragma unroll
        for (int c = 0; c < NCHUNK; c++) {
            #pragma unroll
            for (int i = 0; i < 9; i++) {
                int slot = tid + i * 256;
                int row = slot / 18;
                int cq = slot - row * 18;
                cp16(sb + c * A_STAGE + row * A_PITCH + cq * 16,
                     Xb + (size_t)(b_base + row) * KR + c * KB + cq * 8);
            }
            cp_commit();
        }

        float acc[4][3][4];
        #pragma unroll
        for (int mt = 0; mt < 4; mt++)
            #pragma unroll
            for (int g = 0; g < 3; g++)
                #pragma unroll
                for (int q = 0; q < 4; q++) acc[mt][g][q] = 0.0f;

        // ---- MMA over 2 chunks x 9 k16 ----
        #pragma unroll
        for (int c = 0; c < NCHUNK; c++) {
            if (c == 0) cp_wait<1>();
            else cp_wait<0>();
            __syncthreads();
            const uint32_t aB = sb + c * A_STAGE + a_off;
            #pragma unroll
            for (int kk = 0; kk < 9; kk++) {
                uint32_t af[4][4];
                #pragma unroll
                for (int mt = 0; mt < 4; mt++)
                    ldm_x4(af[mt], aB + mt * (16 * A_PITCH) + kk * 32);
                #pragma unroll
                for (int mt = 0; mt < 4; mt++)
                    #pragma unroll
                    for (int g = 0; g < 3; g++)
                        mma16816(acc[mt][g], af[mt], bfrag[c * 9 + kk][g]);
            }
        }

        // ---- register-local epilogue: gates, state update, direct STG ----
        #pragma unroll
        for (int mt = 0; mt < 4; mt++)
            #pragma unroll
            for (int rr = 0; rr < 2; rr++) {
                uint32_t pk;
                __half2* hp = (__half2*)&pk;
                #pragma unroll
                for (int cc = 0; cc < 2; cc++) {
                    float fp = acc[mt][0][rr * 2 + cc] + bF[cc];
                    float gp = acc[mt][1][rr * 2 + cc] + bG[cc];
                    float op = acc[mt][2][rr * 2 + cc] + bO[cc];
                    float f = sigmoid_fast(fp);
                    float g = tanh_fast(gp);
                    float o = sigmoid_fast(op);
                    float c1 = f * c_r[mt][rr][cc] + ig_r[mt][rr][cc] * g;
                    c_r[mt][rr][cc] = c1;
                    float hv = o * tanh_fast(c1);
                    ((__half*)hp)[cc] = __float2half(hv);
                }
                int b = r_base + mt * 16 + rr * 8;
                *(uint32_t*)(Xo + (size_t)b * KR + hcol) = pk;
            }

        // ---- per-bm release/acquire barrier (monotone counter) ----
        if (t < TT - 1) {
            __syncthreads();
            if (tid == 0) {
                red_release(&g_cnt[bm * 32]);
                const unsigned int target = 8u * (unsigned int)(t + 1);
                while (ld_acquire(&g_cnt[bm * 32]) < target) {}
            }
            __syncthreads();
        }
    }
}

// ---------------- head ----------------
__global__ void head_kernel(const float* __restrict__ pm, float* __restrict__ out)
{
    int b = blockIdx.x * blockDim.x + threadIdx.x;
    if (b >= BB) return;
    const __half* Xrow = &g_X[0][(size_t)b * KR];   // T=128 even -> final h in buffer 0
    float s = g_beff;
    #pragma unroll 8
    for (int k = 0; k < HH; k++)
        s += __half2float(Xrow[k]) * g_weff[k];
    #pragma unroll
    for (int k = 0; k < PMM; k++) s += pm[b * PMM + k] * g_weff[HH + k];
    out[b] = s;
}

// ---------------- launch ----------------
extern "C" void kernel_launch(void* const* d_in, const int* in_sizes, int n_in,
                              void* d_out, int out_size)
{
    const float* x       = (const float*)d_in[0];
    const float* latlons = (const float*)d_in[1];
    const float* yearly  = (const float*)d_in[2];
    const float* pm      = (const float*)d_in[3];
    const float* Wf_i    = (const float*)d_in[4];
    const float* Wf_h    = (const float*)d_in[5];
    const float* bf      = (const float*)d_in[6];
    const float* Wu      = (const float*)d_in[7];
    const float* bu      = (const float*)d_in[8];
    const float* Wg_i    = (const float*)d_in[9];
    const float* Wg_h    = (const float*)d_in[10];
    const float* bg      = (const float*)d_in[11];
    const float* Wo_i    = (const float*)d_in[12];
    const float* Wo_h    = (const float*)d_in[13];
    const float* bo      = (const float*)d_in[14];
    const float* Wd0     = (const float*)d_in[15];
    const float* bd0     = (const float*)d_in[16];
    const float* Wd1     = (const float*)d_in[17];
    const float* bd1     = (const float*)d_in[18];

    static bool attr_set = false;
    if (!attr_set) {
        cudaFuncSetAttribute(step_persist, cudaFuncAttributeMaxDynamicSharedMemorySize, SMEM_TOTAL);
        attr_set = true;
    }

    prep_all<<<289, 256>>>(x, Wd0, bd0, Wd1, bd1);

    step_persist<<<dim3(16, 8), 256, SMEM_TOTAL>>>(
        x, latlons, yearly, Wu, bu,
        Wf_i, Wf_h, bf, Wg_i, Wg_h, bg, Wo_i, Wo_h, bo);

    head_kernel<<<(BB + 255) / 256, 256>>>(pm, (float*)d_out);
}

// round 11
// speedup vs baseline: 5.2120x; 1.0286x over previous
#include <cuda_runtime.h>
#include <cuda_fp16.h>
#include <math.h>
#include <stdint.h>

#define BB 2048
#define TT 128
#define DD 32
#define HH 256
#define SS 39
#define PMM 12
#define KR 288              /* k layout: [h 256 | x 32] */
#define NCHUNK 2
#define KB 144
#define NK16 18             /* 288/16 */

/* smem layout (bytes) */
#define A_PITCH 304                       /* 152 halfs: 144 data + 8 pad, odd x 16B */
#define A_STAGE (128 * A_PITCH)           /* 38912 */
#define W_ORIGIN (2 * A_STAGE)            /* 77824 */
#define W_PITCH 208                       /* 104 halfs: 96 data + 8 pad */
#define SMEM_TOTAL (W_ORIGIN + KR * W_PITCH)   /* 137728 */

// ---------------- device scratch ----------------
__device__ __half g_X[2][BB * KR];               // activations [b][k], ping-pong
__device__ float g_weff[HH + PMM];
__device__ float g_beff;
__device__ unsigned int g_cnt[16 * 32];          // per-bm monotone arrival counters (128B apart)

// ---------------- asm helpers ----------------
__device__ __forceinline__ uint32_t smem_u32(const void* p) {
    uint32_t a;
    asm("{ .reg .u64 t; cvta.to.shared.u64 t, %1; cvt.u32.u64 %0, t; }" : "=r"(a) : "l"(p));
    return a;
}
__device__ __forceinline__ void cp16(uint32_t dst, const void* src) {
    asm volatile("cp.async.cg.shared.global [%0], [%1], 16;" :: "r"(dst), "l"(src) : "memory");
}
__device__ __forceinline__ void cp_commit() {
    asm volatile("cp.async.commit_group;" ::: "memory");
}
template <int N>
__device__ __forceinline__ void cp_wait() {
    asm volatile("cp.async.wait_group %0;" :: "n"(N) : "memory");
}
__device__ __forceinline__ void ldm_x4(uint32_t* r, uint32_t addr) {
    asm volatile("ldmatrix.sync.aligned.m8n8.x4.shared.b16 {%0,%1,%2,%3}, [%4];"
                 : "=r"(r[0]), "=r"(r[1]), "=r"(r[2]), "=r"(r[3]) : "r"(addr));
}
__device__ __forceinline__ void ldm_x2t(uint32_t* r, uint32_t addr) {
    asm volatile("ldmatrix.sync.aligned.m8n8.x2.trans.shared.b16 {%0,%1}, [%2];"
                 : "=r"(r[0]), "=r"(r[1]) : "r"(addr));
}
__device__ __forceinline__ void mma16816(float* d, const uint32_t* a, const uint32_t* b) {
    asm volatile(
        "mma.sync.aligned.m16n8k16.row.col.f32.f16.f16.f32 "
        "{%0,%1,%2,%3}, {%4,%5,%6,%7}, {%8,%9}, {%0,%1,%2,%3};"
        : "+f"(d[0]), "+f"(d[1]), "+f"(d[2]), "+f"(d[3])
        : "r"(a[0]), "r"(a[1]), "r"(a[2]), "r"(a[3]), "r"(b[0]), "r"(b[1]));
}
__device__ __forceinline__ float tanh_fast(float x) {
    float y;
    asm("tanh.approx.f32 %0, %1;" : "=f"(y) : "f"(x));
    return y;
}
__device__ __forceinline__ float sigmoid_fast(float x) {
    return fmaf(0.5f, tanh_fast(0.5f * x), 0.5f);
}
__device__ __forceinline__ void red_release(unsigned int* p) {
    asm volatile("red.release.gpu.global.add.u32 [%0], 1;" :: "l"(p) : "memory");
}
__device__ __forceinline__ unsigned int ld_acquire(const unsigned int* p) {
    unsigned int v;
    asm volatile("ld.acquire.gpu.global.u32 %0, [%1];" : "=r"(v) : "l"(p) : "memory");
    return v;
}

// ---------------- prep: warp-parallel head collapse + counters (34 blocks) ----------------
__global__ void prep_head(const float* __restrict__ Wd0, const float* __restrict__ bd0,
                          const float* __restrict__ Wd1, const float* __restrict__ bd1)
{
    const int gw = blockIdx.x * 8 + (threadIdx.x >> 5);   // global warp id
    const int lane = threadIdx.x & 31;
    if (gw < HH + PMM) {
        float s = 0.0f;
        #pragma unroll
        for (int i = 0; i < 8; i++) {
            int m = i * 32 + lane;
            s += Wd1[m] * Wd0[m * (HH + PMM) + gw];
        }
        #pragma unroll
        for (int off = 16; off > 0; off >>= 1)
            s += __shfl_xor_sync(0xFFFFFFFFu, s, off);
        if (lane == 0) g_weff[gw] = s;
    } else if (gw == HH + PMM) {
        float s = 0.0f;
        #pragma unroll
        for (int i = 0; i < 8; i++) {
            int m = i * 32 + lane;
            s += Wd1[m] * bd0[m];
        }
        #pragma unroll
        for (int off = 16; off > 0; off >>= 1)
            s += __shfl_xor_sync(0xFFFFFFFFu, s, off);
        if (lane == 0) g_beff = s + bd1[0];
        if (lane < 16) g_cnt[lane * 32] = 0;
    }
}

// ---------------- persistent recurrent kernel ----------------
// 128 CTAs (16 bm x 8 jt), 1 CTA/SM. X0 init folded into prologue (extra barrier round).
__global__ void __launch_bounds__(256, 1) step_persist(
    const float* __restrict__ xg,
    const float* __restrict__ latlons, const float* __restrict__ yearly,
    const float* __restrict__ Wu, const float* __restrict__ bu,
    const float* __restrict__ Wf_i, const float* __restrict__ Wf_h, const float* __restrict__ bf,
    const float* __restrict__ Wg_i, const float* __restrict__ Wg_h, const float* __restrict__ bg,
    const float* __restrict__ Wo_i, const float* __restrict__ Wo_h, const float* __restrict__ bo)
{
    extern __shared__ char smem[];
    const uint32_t sb = smem_u32(smem);
    const int tid = threadIdx.x;
    const int lane = tid & 31;
    const int wid = tid >> 5;
    const int wm = wid & 1;           // 0..1 (64 batch rows)
    const int wn = wid >> 1;          // 0..3 (8 h cols)
    const int bm = blockIdx.x;        // 0..15
    const int jt = blockIdx.y;        // 0..7
    const int b_base = bm * 128;
    const int h0 = jt * 32;

    // thread's fixed (b,h) ownership
    const int r_base = b_base + wm * 64 + (lane >> 2);    // + mt*16 + rr*8
    const int hcol = h0 + wn * 8 + (lane & 3) * 2;        // 2 consecutive h

    // ---- prologue: W tile gathered DIRECTLY from raw fp32 weights -> SMEM ----
    {
        __half* Wrow = (__half*)(smem + W_ORIGIN);
        #pragma unroll
        for (int ci = 0; ci < 12; ci++) {
            int col = wid * 12 + ci;
            int gate = col >> 5;              // 0..2
            int hh = col & 31;
            const float* Whg = (gate == 0) ? Wf_h : (gate == 1) ? Wg_h : Wo_h;
            const float* Wig = (gate == 0) ? Wf_i : (gate == 1) ? Wg_i : Wo_i;
            const float* hrow = Whg + (size_t)(h0 + hh) * HH;
            const float* irow = Wig + (size_t)(h0 + hh) * DD;
            #pragma unroll
            for (int it = 0; it < 9; it++) {
                int k = it * 32 + lane;
                float v = (k < HH) ? hrow[k] : irow[k - HH];
                Wrow[k * 104 + col] = __float2half(v);
            }
        }
    }

    // ---- prologue: bias direct LDG ----
    float bF[2], bG[2], bO[2];
    #pragma unroll
    for (int cc = 0; cc < 2; cc++) {
        bF[cc] = bf[hcol + cc];
        bG[cc] = bg[hcol + cc];
        bO[cc] = bo[hcol + cc];
    }

    // ---- prologue: i_gate computed in-place into registers, c = 0 ----
    float c_r[4][2][2];
    float ig_r[4][2][2];
    #pragma unroll
    for (int mt = 0; mt < 4; mt++)
        #pragma unroll
        for (int rr = 0; rr < 2; rr++) {
            const int b = r_base + mt * 16 + rr * 8;
            const float ll0 = latlons[b * 2 + 0];
            const float ll1 = latlons[b * 2 + 1];
            const float* yr = yearly + (size_t)b * 37;
            #pragma unroll
            for (int cc = 0; cc < 2; cc++) {
                const int h = hcol + cc;
                const float* w = Wu + h * SS;
                float s = bu[h] + w[0] * ll0 + w[1] * ll1;
                #pragma unroll
                for (int i = 0; i < 37; i++) s += w[2 + i] * yr[i];
                ig_r[mt][rr][cc] = sigmoid_fast(s);
                c_r[mt][rr][cc] = 0.0f;
            }
        }

    // ---- prologue: init X[0] in place (h part = 0 via ownership; x part by jt0) ----
    #pragma unroll
    for (int mt = 0; mt < 4; mt++)
        #pragma unroll
        for (int rr = 0; rr < 2; rr++) {
            int b = r_base + mt * 16 + rr * 8;
            *(uint32_t*)(&g_X[0][(size_t)b * KR + hcol]) = 0u;
        }
    if (jt == 0 && tid < 128) {
        const int b = b_base + tid;
        const float* xr = xg + (size_t)b * (TT * DD);
        __half* dst = &g_X[0][(size_t)b * KR + HH];
        #pragma unroll
        for (int i = 0; i < 4; i++) {
            float4 v0 = *(const float4*)(xr + i * 8);
            float4 v1 = *(const float4*)(xr + i * 8 + 4);
            __half2 p0 = __floats2half2_rn(v0.x, v0.y);
            __half2 p1 = __floats2half2_rn(v0.z, v0.w);
            __half2 p2 = __floats2half2_rn(v1.x, v1.y);
            __half2 p3 = __floats2half2_rn(v1.z, v1.w);
            uint4 pk = make_uint4(*(uint32_t*)&p0, *(uint32_t*)&p1,
                                  *(uint32_t*)&p2, *(uint32_t*)&p3);
            *(uint4*)(dst + i * 8) = pk;
        }
    }
    __syncthreads();

    // ---- hoist W fragments into registers (gate = nt) ----
    uint32_t bfrag[NK16][3][2];
    {
        const uint32_t wb = sb + W_ORIGIN + (lane & 15) * W_PITCH + wn * 16;
        #pragma unroll
        for (int k16 = 0; k16 < NK16; k16++)
            #pragma unroll
            for (int gate = 0; gate < 3; gate++)
                ldm_x2t(bfrag[k16][gate], wb + k16 * (16 * W_PITCH) + gate * 64);
    }

    // ---- barrier round 1: X[0] visible across the bm group before first load ----
    if (tid == 0) {
        red_release(&g_cnt[bm * 32]);
        while (ld_acquire(&g_cnt[bm * 32]) < 8u) {}
    }
    __syncthreads();

    const uint32_t a_off = (uint32_t)((wm * 64 + (lane & 15)) * A_PITCH + (lane >> 4) * 16);

    for (int t = 0; t < TT; t++) {
        const __half* __restrict__ Xb = g_X[t & 1];
        __half* Xo = &g_X[(t + 1) & 1][0];

        // ---- on-the-fly x convert for t+1 (latency hidden behind MMA phase) ----
        if (jt == 0 && t < TT - 1 && tid < 128) {
            const int b = b_base + tid;
            const float* xr = xg + (size_t)b * (TT * DD) + (size_t)(t + 1) * DD;
            __half* dst = Xo + (size_t)b * KR + HH;
            #pragma unroll
            for (int i = 0; i < 4; i++) {
                float4 v0 = *(const float4*)(xr + i * 8);
                float4 v1 = *(const float4*)(xr + i * 8 + 4);
                __half2 p0 = __floats2half2_rn(v0.x, v0.y);
                __half2 p1 = __floats2half2_rn(v0.z, v0.w);
                __half2 p2 = __floats2half2_rn(v1.x, v1.y);
                __half2 p3 = __floats2half2_rn(v1.z, v1.w);
                uint4 pk = make_uint4(*(uint32_t*)&p0, *(uint32_t*)&p1,
                                      *(uint32_t*)&p2, *(uint32_t*)&p3);
                *(uint4*)(dst + i * 8) = pk;
            }
        }

        // ---- issue both A chunks (cp.async.cg: L2-only) ----
        #pragma unroll
        for (int c = 0; c < NCHUNK; c++) {
            #pragma unroll
            for (int i = 0; i < 9; i++) {
                int slot = tid + i * 256;
                int row = slot / 18;
                int cq = slot - row * 18;
                cp16(sb + c * A_STAGE + row * A_PITCH + cq * 16,
                     Xb + (size_t)(b_base + row) * KR + c * KB + cq * 8);
            }
            cp_commit();
        }

        float acc[4][3][4];
        #pragma unroll
        for (int mt = 0; mt < 4; mt++)
            #pragma unroll
            for (int g = 0; g < 3; g++)
                #pragma unroll
                for (int q = 0; q < 4; q++) acc[mt][g][q] = 0.0f;

        // ---- MMA over 2 chunks x 9 k16 ----
        #pragma unroll
        for (int c = 0; c < NCHUNK; c++) {
            if (c == 0) cp_wait<1>();
            else cp_wait<0>();
            __syncthreads();
            const uint32_t aB = sb + c * A_STAGE + a_off;
            #pragma unroll
            for (int kk = 0; kk < 9; kk++) {
                uint32_t af[4][4];
                #pragma unroll
                for (int mt = 0; mt < 4; mt++)
                    ldm_x4(af[mt], aB + mt * (16 * A_PITCH) + kk * 32);
                #pragma unroll
                for (int mt = 0; mt < 4; mt++)
                    #pragma unroll
                    for (int g = 0; g < 3; g++)
                        mma16816(acc[mt][g], af[mt], bfrag[c * 9 + kk][g]);
            }
        }

        // ---- register-local epilogue: gates, state update, direct STG ----
        #pragma unroll
        for (int mt = 0; mt < 4; mt++)
            #pragma unroll
            for (int rr = 0; rr < 2; rr++) {
                uint32_t pk;
                __half2* hp = (__half2*)&pk;
                #pragma unroll
                for (int cc = 0; cc < 2; cc++) {
                    float fp = acc[mt][0][rr * 2 + cc] + bF[cc];
                    float gp = acc[mt][1][rr * 2 + cc] + bG[cc];
                    float op = acc[mt][2][rr * 2 + cc] + bO[cc];
                    float f = sigmoid_fast(fp);
                    float g = tanh_fast(gp);
                    float o = sigmoid_fast(op);
                    float c1 = f * c_r[mt][rr][cc] + ig_r[mt][rr][cc] * g;
                    c_r[mt][rr][cc] = c1;
                    float hv = o * tanh_fast(c1);
                    ((__half*)hp)[cc] = __float2half(hv);
                }
                int b = r_base + mt * 16 + rr * 8;
                *(uint32_t*)(Xo + (size_t)b * KR + hcol) = pk;
            }

        // ---- per-bm release/acquire barrier (round t+2) ----
        if (t < TT - 1) {
            __syncthreads();
            if (tid == 0) {
                red_release(&g_cnt[bm * 32]);
                const unsigned int target = 8u * (unsigned int)(t + 2);
                while (ld_acquire(&g_cnt[bm * 32]) < target) {}
            }
            __syncthreads();
        }
    }
}

// ---------------- head (vectorized h loads) ----------------
__global__ void head_kernel(const float* __restrict__ pm, float* __restrict__ out)
{
    int b = blockIdx.x * blockDim.x + threadIdx.x;
    if (b >= BB) return;
    const __half* Xrow = &g_X[0][(size_t)b * KR];   // T=128 even -> final h in buffer 0
    float s = g_beff;
    #pragma unroll
    for (int i = 0; i < 32; i++) {
        uint4 v = *(const uint4*)(Xrow + i * 8);
        const __half2* hp = (const __half2*)&v;
        #pragma unroll
        for (int q = 0; q < 4; q++) {
            float2 f = __half22float2(hp[q]);
            s += f.x * g_weff[i * 8 + q * 2];
            s += f.y * g_weff[i * 8 + q * 2 + 1];
        }
    }
    #pragma unroll
    for (int k = 0; k < PMM; k++) s += pm[b * PMM + k] * g_weff[HH + k];
    out[b] = s;
}

// ---------------- launch ----------------
extern "C" void kernel_launch(void* const* d_in, const int* in_sizes, int n_in,
                              void* d_out, int out_size)
{
    const float* x       = (const float*)d_in[0];
    const float* latlons = (const float*)d_in[1];
    const float* yearly  = (const float*)d_in[2];
    const float* pm      = (const float*)d_in[3];
    const float* Wf_i    = (const float*)d_in[4];
    const float* Wf_h    = (const float*)d_in[5];
    const float* bf      = (const float*)d_in[6];
    const float* Wu      = (const float*)d_in[7];
    const float* bu      = (const float*)d_in[8];
    const float* Wg_i    = (const float*)d_in[9];
    const float* Wg_h    = (const float*)d_in[10];
    const float* bg      = (const float*)d_in[11];
    const float* Wo_i    = (const float*)d_in[12];
    const float* Wo_h    = (const float*)d_in[13];
    const float* bo      = (const float*)d_in[14];
    const float* Wd0     = (const float*)d_in[15];
    const float* bd0     = (const float*)d_in[16];
    const float* Wd1     = (const float*)d_in[17];
    const float* bd1     = (const float*)d_in[18];

    static bool attr_set = false;
    if (!attr_set) {
        cudaFuncSetAttribute(step_persist, cudaFuncAttributeMaxDynamicSharedMemorySize, SMEM_TOTAL);
        attr_set = true;
    }

    prep_head<<<34, 256>>>(Wd0, bd0, Wd1, bd1);

    step_persist<<<dim3(16, 8), 256, SMEM_TOTAL>>>(
        x, latlons, yearly, Wu, bu,
        Wf_i, Wf_h, bf, Wg_i, Wg_h, bg, Wo_i, Wo_h, bo);

    head_kernel<<<(BB + 255) / 256, 256>>>(pm, (float*)d_out);
}

// round 12
// speedup vs baseline: 5.3443x; 1.0254x over previous
#include <cuda_runtime.h>
#include <cuda_fp16.h>
#include <math.h>
#include <stdint.h>

#define BB 2048
#define TT 128
#define DD 32
#define HH 256
#define SS 39
#define PMM 12
#define KR 288              /* k layout: [h 256 | x 32] */
#define NCHUNK 2
#define KB 144
#define NK16 18             /* 288/16 */

/* smem layout (bytes) */
#define A_PITCH 304                       /* 152 halfs: 144 data + 8 pad, odd x 16B */
#define A_STAGE (128 * A_PITCH)           /* 38912 */
#define W_ORIGIN (2 * A_STAGE)            /* 77824 */
#define W_PITCH 208                       /* 104 halfs: 96 data + 8 pad */
#define SMEM_TOTAL (W_ORIGIN + KR * W_PITCH)   /* 137728 */

// ---------------- device scratch ----------------
__device__ __half g_X[2][BB * KR];               // activations [b][k], ping-pong
__device__ float g_weff[HH + PMM];
__device__ float g_beff;
__device__ unsigned int g_cnt[16 * 32];          // per-bm monotone arrival counters (128B apart)

// ---------------- asm helpers ----------------
__device__ __forceinline__ uint32_t smem_u32(const void* p) {
    uint32_t a;
    asm("{ .reg .u64 t; cvta.to.shared.u64 t, %1; cvt.u32.u64 %0, t; }" : "=r"(a) : "l"(p));
    return a;
}
__device__ __forceinline__ void cp16(uint32_t dst, const void* src) {
    asm volatile("cp.async.cg.shared.global [%0], [%1], 16;" :: "r"(dst), "l"(src) : "memory");
}
__device__ __forceinline__ void cp_commit() {
    asm volatile("cp.async.commit_group;" ::: "memory");
}
template <int N>
__device__ __forceinline__ void cp_wait() {
    asm volatile("cp.async.wait_group %0;" :: "n"(N) : "memory");
}
__device__ __forceinline__ void ldm_x4(uint32_t* r, uint32_t addr) {
    asm volatile("ldmatrix.sync.aligned.m8n8.x4.shared.b16 {%0,%1,%2,%3}, [%4];"
                 : "=r"(r[0]), "=r"(r[1]), "=r"(r[2]), "=r"(r[3]) : "r"(addr));
}
__device__ __forceinline__ void ldm_x2t(uint32_t* r, uint32_t addr) {
    asm volatile("ldmatrix.sync.aligned.m8n8.x2.trans.shared.b16 {%0,%1}, [%2];"
                 : "=r"(r[0]), "=r"(r[1]) : "r"(addr));
}
__device__ __forceinline__ void mma16816(float* d, const uint32_t* a, const uint32_t* b) {
    asm volatile(
        "mma.sync.aligned.m16n8k16.row.col.f32.f16.f16.f32 "
        "{%0,%1,%2,%3}, {%4,%5,%6,%7}, {%8,%9}, {%0,%1,%2,%3};"
        : "+f"(d[0]), "+f"(d[1]), "+f"(d[2]), "+f"(d[3])
        : "r"(a[0]), "r"(a[1]), "r"(a[2]), "r"(a[3]), "r"(b[0]), "r"(b[1]));
}
__device__ __forceinline__ float tanh_fast(float x) {
    float y;
    asm("tanh.approx.f32 %0, %1;" : "=f"(y) : "f"(x));
    return y;
}
__device__ __forceinline__ float sigmoid_fast(float x) {
    return fmaf(0.5f, tanh_fast(0.5f * x), 0.5f);
}
__device__ __forceinline__ uint32_t tanh_h2(uint32_t x) {
    uint32_t y;
    asm("tanh.approx.f16x2 %0, %1;" : "=r"(y) : "r"(x));
    return y;
}
__device__ __forceinline__ uint32_t pack_h2(float a, float b) {
    __half2 h = __floats2half2_rn(a, b);
    return *(uint32_t*)&h;
}
__device__ __forceinline__ __half2 u2h(uint32_t u) { return *(__half2*)&u; }
__device__ __forceinline__ void red_release(unsigned int* p) {
    asm volatile("red.release.gpu.global.add.u32 [%0], 1;" :: "l"(p) : "memory");
}
__device__ __forceinline__ unsigned int ld_acquire(const unsigned int* p) {
    unsigned int v;
    asm volatile("ld.acquire.gpu.global.u32 %0, [%1];" : "=r"(v) : "l"(p) : "memory");
    return v;
}

// ---------------- prep: warp-parallel head collapse + counters + out zero (34 blocks) ----------------
__global__ void prep_head(const float* __restrict__ Wd0, const float* __restrict__ bd0,
                          const float* __restrict__ Wd1, const float* __restrict__ bd1,
                          float* __restrict__ out)
{
    const int gw = blockIdx.x * 8 + (threadIdx.x >> 5);   // global warp id
    const int lane = threadIdx.x & 31;
    const int gid = blockIdx.x * 256 + threadIdx.x;
    if (gid < BB) out[gid] = 0.0f;
    if (gw < HH + PMM) {
        float s = 0.0f;
        #pragma unroll
        for (int i = 0; i < 8; i++) {
            int m = i * 32 + lane;
            s += Wd1[m] * Wd0[m * (HH + PMM) + gw];
        }
        #pragma unroll
        for (int off = 16; off > 0; off >>= 1)
            s += __shfl_xor_sync(0xFFFFFFFFu, s, off);
        if (lane == 0) g_weff[gw] = s;
    } else if (gw == HH + PMM) {
        float s = 0.0f;
        #pragma unroll
        for (int i = 0; i < 8; i++) {
            int m = i * 32 + lane;
            s += Wd1[m] * bd0[m];
        }
        #pragma unroll
        for (int off = 16; off > 0; off >>= 1)
            s += __shfl_xor_sync(0xFFFFFFFFu, s, off);
        if (lane == 0) g_beff = s + bd1[0];
        if (lane < 16) g_cnt[lane * 32] = 0;
    }
}

// ---------------- persistent recurrent kernel (head folded in) ----------------
__global__ void __launch_bounds__(256, 1) step_persist(
    const float* __restrict__ xg,
    const float* __restrict__ latlons, const float* __restrict__ yearly,
    const float* __restrict__ Wu, const float* __restrict__ bu,
    const float* __restrict__ Wf_i, const float* __restrict__ Wf_h, const float* __restrict__ bf,
    const float* __restrict__ Wg_i, const float* __restrict__ Wg_h, const float* __restrict__ bg,
    const float* __restrict__ Wo_i, const float* __restrict__ Wo_h, const float* __restrict__ bo,
    const float* __restrict__ pm, float* __restrict__ out)
{
    extern __shared__ char smem[];
    const uint32_t sb = smem_u32(smem);
    const int tid = threadIdx.x;
    const int lane = tid & 31;
    const int wid = tid >> 5;
    const int wm = wid & 1;           // 0..1 (64 batch rows)
    const int wn = wid >> 1;          // 0..3 (8 h cols)
    const int bm = blockIdx.x;        // 0..15
    const int jt = blockIdx.y;        // 0..7
    const int b_base = bm * 128;
    const int h0 = jt * 32;

    // thread's fixed (b,h) ownership
    const int r_base = b_base + wm * 64 + (lane >> 2);    // + mt*16 + rr*8
    const int hcol = h0 + wn * 8 + (lane & 3) * 2;        // 2 consecutive h

    // ---- prologue: W tile gathered DIRECTLY from raw fp32 weights -> SMEM ----
    {
        __half* Wrow = (__half*)(smem + W_ORIGIN);
        #pragma unroll
        for (int ci = 0; ci < 12; ci++) {
            int col = wid * 12 + ci;
            int gate = col >> 5;              // 0..2
            int hh = col & 31;
            const float* Whg = (gate == 0) ? Wf_h : (gate == 1) ? Wg_h : Wo_h;
            const float* Wig = (gate == 0) ? Wf_i : (gate == 1) ? Wg_i : Wo_i;
            const float* hrow = Whg + (size_t)(h0 + hh) * HH;
            const float* irow = Wig + (size_t)(h0 + hh) * DD;
            #pragma unroll
            for (int it = 0; it < 9; it++) {
                int k = it * 32 + lane;
                float v = (k < HH) ? hrow[k] : irow[k - HH];
                Wrow[k * 104 + col] = __float2half(v);
            }
        }
    }

    // ---- prologue: bias (sigmoid ones pre-scaled by 0.5) + head weights ----
    float bFh[2], bG[2], bOh[2];
    #pragma unroll
    for (int cc = 0; cc < 2; cc++) {
        bFh[cc] = bf[hcol + cc] * 0.5f;
        bG[cc]  = bg[hcol + cc];
        bOh[cc] = bo[hcol + cc] * 0.5f;
    }
    const float wf0 = g_weff[hcol];
    const float wf1 = g_weff[hcol + 1];
    const __half2 h05 = __float2half2_rn(0.5f);

    // ---- prologue: i_gate computed in-place into registers, c = 0 ----
    float c_r[4][2][2];
    float ig_r[4][2][2];
    #pragma unroll
    for (int mt = 0; mt < 4; mt++)
        #pragma unroll
        for (int rr = 0; rr < 2; rr++) {
            const int b = r_base + mt * 16 + rr * 8;
            const float ll0 = latlons[b * 2 + 0];
            const float ll1 = latlons[b * 2 + 1];
            const float* yr = yearly + (size_t)b * 37;
            #pragma unroll
            for (int cc = 0; cc < 2; cc++) {
                const int h = hcol + cc;
                const float* w = Wu + h * SS;
                float s = bu[h] + w[0] * ll0 + w[1] * ll1;
                #pragma unroll
                for (int i = 0; i < 37; i++) s += w[2 + i] * yr[i];
                ig_r[mt][rr][cc] = sigmoid_fast(s);
                c_r[mt][rr][cc] = 0.0f;
            }
        }

    // ---- prologue: init X[0] in place ----
    #pragma unroll
    for (int mt = 0; mt < 4; mt++)
        #pragma unroll
        for (int rr = 0; rr < 2; rr++) {
            int b = r_base + mt * 16 + rr * 8;
            *(uint32_t*)(&g_X[0][(size_t)b * KR + hcol]) = 0u;
        }
    if (jt == 0 && tid < 128) {
        const int b = b_base + tid;
        const float* xr = xg + (size_t)b * (TT * DD);
        __half* dst = &g_X[0][(size_t)b * KR + HH];
        #pragma unroll
        for (int i = 0; i < 4; i++) {
            float4 v0 = *(const float4*)(xr + i * 8);
            float4 v1 = *(const float4*)(xr + i * 8 + 4);
            uint4 pk = make_uint4(pack_h2(v0.x, v0.y), pack_h2(v0.z, v0.w),
                                  pack_h2(v1.x, v1.y), pack_h2(v1.z, v1.w));
            *(uint4*)(dst + i * 8) = pk;
        }
    }
    __syncthreads();

    // ---- hoist W fragments into registers (gate = nt) ----
    uint32_t bfrag[NK16][3][2];
    {
        const uint32_t wb = sb + W_ORIGIN + (lane & 15) * W_PITCH + wn * 16;
        #pragma unroll
        for (int k16 = 0; k16 < NK16; k16++)
            #pragma unroll
            for (int gate = 0; gate < 3; gate++)
                ldm_x2t(bfrag[k16][gate], wb + k16 * (16 * W_PITCH) + gate * 64);
    }

    // ---- barrier round 1: X[0] visible across the bm group ----
    if (tid == 0) {
        red_release(&g_cnt[bm * 32]);
        while (ld_acquire(&g_cnt[bm * 32]) < 8u) {}
    }
    __syncthreads();

    const uint32_t a_off = (uint32_t)((wm * 64 + (lane & 15)) * A_PITCH + (lane >> 4) * 16);
    uint32_t hl[4][2];   // last-step h (packed half2) for folded head

    for (int t = 0; t < TT; t++) {
        const __half* __restrict__ Xb = g_X[t & 1];
        __half* Xo = &g_X[(t + 1) & 1][0];

        // ---- on-the-fly x convert for t+1 ----
        if (jt == 0 && t < TT - 1 && tid < 128) {
            const int b = b_base + tid;
            const float* xr = xg + (size_t)b * (TT * DD) + (size_t)(t + 1) * DD;
            __half* dst = Xo + (size_t)b * KR + HH;
            #pragma unroll
            for (int i = 0; i < 4; i++) {
                float4 v0 = *(const float4*)(xr + i * 8);
                float4 v1 = *(const float4*)(xr + i * 8 + 4);
                uint4 pk = make_uint4(pack_h2(v0.x, v0.y), pack_h2(v0.z, v0.w),
                                      pack_h2(v1.x, v1.y), pack_h2(v1.z, v1.w));
                *(uint4*)(dst + i * 8) = pk;
            }
        }

        // ---- issue both A chunks (cp.async.cg: L2-only) ----
        #pragma unroll
        for (int c = 0; c < NCHUNK; c++) {
            #pragma unroll
            for (int i = 0; i < 9; i++) {
                int slot = tid + i * 256;
                int row = slot / 18;
                int cq = slot - row * 18;
                cp16(sb + c * A_STAGE + row * A_PITCH + cq * 16,
                     Xb + (size_t)(b_base + row) * KR + c * KB + cq * 8);
            }
            cp_commit();
        }

        float acc[4][3][4];
        #pragma unroll
        for (int mt = 0; mt < 4; mt++)
            #pragma unroll
            for (int g = 0; g < 3; g++)
                #pragma unroll
                for (int q = 0; q < 4; q++) acc[mt][g][q] = 0.0f;

        // ---- MMA over 2 chunks x 9 k16 ----
        #pragma unroll
        for (int c = 0; c < NCHUNK; c++) {
            if (c == 0) cp_wait<1>();
            else cp_wait<0>();
            __syncthreads();
            const uint32_t aB = sb + c * A_STAGE + a_off;
            #pragma unroll
            for (int kk = 0; kk < 9; kk++) {
                uint32_t af[4][4];
                #pragma unroll
                for (int mt = 0; mt < 4; mt++)
                    ldm_x4(af[mt], aB + mt * (16 * A_PITCH) + kk * 32);
                #pragma unroll
                for (int mt = 0; mt < 4; mt++)
                    #pragma unroll
                    for (int g = 0; g < 3; g++)
                        mma16816(acc[mt][g], af[mt], bfrag[c * 9 + kk][g]);
            }
        }

        // ---- f16x2 epilogue: gates via tanh.approx.f16x2, c stays fp32 ----
        #pragma unroll
        for (int mt = 0; mt < 4; mt++)
            #pragma unroll
            for (int rr = 0; rr < 2; rr++) {
                uint32_t fi = pack_h2(fmaf(acc[mt][0][rr * 2],     0.5f, bFh[0]),
                                      fmaf(acc[mt][0][rr * 2 + 1], 0.5f, bFh[1]));
                __half2 f2 = __hfma2(u2h(tanh_h2(fi)), h05, h05);
                float2 ff = __half22float2(f2);
                uint32_t gi = pack_h2(acc[mt][1][rr * 2] + bG[0],
                                      acc[mt][1][rr * 2 + 1] + bG[1]);
                float2 gg = __half22float2(u2h(tanh_h2(gi)));
                uint32_t oi = pack_h2(fmaf(acc[mt][2][rr * 2],     0.5f, bOh[0]),
                                      fmaf(acc[mt][2][rr * 2 + 1], 0.5f, bOh[1]));
                __half2 o2 = __hfma2(u2h(tanh_h2(oi)), h05, h05);
                float c10 = ff.x * c_r[mt][rr][0] + ig_r[mt][rr][0] * gg.x;
                float c11 = ff.y * c_r[mt][rr][1] + ig_r[mt][rr][1] * gg.y;
                c_r[mt][rr][0] = c10;
                c_r[mt][rr][1] = c11;
                __half2 hv2 = __hmul2(o2, u2h(tanh_h2(pack_h2(c10, c11))));
                uint32_t pk = *(uint32_t*)&hv2;
                int b = r_base + mt * 16 + rr * 8;
                *(uint32_t*)(Xo + (size_t)b * KR + hcol) = pk;
                if (t == TT - 1) hl[mt][rr] = pk;
            }

        // ---- per-bm release/acquire barrier (round t+2) ----
        if (t < TT - 1) {
            __syncthreads();
            if (tid == 0) {
                red_release(&g_cnt[bm * 32]);
                const unsigned int target = 8u * (unsigned int)(t + 2);
                while (ld_acquire(&g_cnt[bm * 32]) < target) {}
            }
            __syncthreads();
        }
    }

    // ---- folded head: partial dot + quad reduce + atomicAdd ----
    #pragma unroll
    for (int mt = 0; mt < 4; mt++)
        #pragma unroll
        for (int rr = 0; rr < 2; rr++) {
            float2 hf = __half22float2(u2h(hl[mt][rr]));
            float p = hf.x * wf0 + hf.y * wf1;
            p += __shfl_xor_sync(0xFFFFFFFFu, p, 1);
            p += __shfl_xor_sync(0xFFFFFFFFu, p, 2);
            if ((lane & 3) == 0)
                atomicAdd(out + r_base + mt * 16 + rr * 8, p);
        }
    if (jt == 0 && tid < 128) {
        const int b = b_base + tid;
        float s = g_beff;
        #pragma unroll
        for (int k = 0; k < PMM; k++) s += pm[b * PMM + k] * g_weff[HH + k];
        atomicAdd(out + b, s);
    }
}

// ---------------- launch ----------------
extern "C" void kernel_launch(void* const* d_in, const int* in_sizes, int n_in,
                              void* d_out, int out_size)
{
    const float* x       = (const float*)d_in[0];
    const float* latlons = (const float*)d_in[1];
    const float* yearly  = (const float*)d_in[2];
    const float* pm      = (const float*)d_in[3];
    const float* Wf_i    = (const float*)d_in[4];
    const float* Wf_h    = (const float*)d_in[5];
    const float* bf      = (const float*)d_in[6];
    const float* Wu      = (const float*)d_in[7];
    const float* bu      = (const float*)d_in[8];
    const float* Wg_i    = (const float*)d_in[9];
    const float* Wg_h    = (const float*)d_in[10];
    const float* bg      = (const float*)d_in[11];
    const float* Wo_i    = (const float*)d_in[12];
    const float* Wo_h    = (const float*)d_in[13];
    const float* bo      = (const float*)d_in[14];
    const float* Wd0     = (const float*)d_in[15];
    const float* bd0     = (const float*)d_in[16];
    const float* Wd1     = (const float*)d_in[17];
    const float* bd1     = (const float*)d_in[18];

    static bool attr_set = false;
    if (!attr_set) {
        cudaFuncSetAttribute(step_persist, cudaFuncAttributeMaxDynamicSharedMemorySize, SMEM_TOTAL);
        attr_set = true;
    }

    prep_head<<<34, 256>>>(Wd0, bd0, Wd1, bd1, (float*)d_out);

    step_persist<<<dim3(16, 8), 256, SMEM_TOTAL>>>(
        x, latlons, yearly, Wu, bu,
        Wf_i, Wf_h, bf, Wg_i, Wg_h, bg, Wo_i, Wo_h, bo,
        pm, (float*)d_out);
}